// round 2
// baseline (speedup 1.0000x reference)
#include <cuda_runtime.h>

// ---------------- problem constants (fixed shapes) ----------------
#define B_    32
#define E_    256
#define N_    512          // 2E nodes
#define HID   64           // hidden
#define H_    4            // heads
#define F_    64           // per-head feature
#define C_    256          // H*F
#define S_    255          // E-1 shot steps
#define NE_ELEMS (B_*N_*C_)          // 4,194,304
#define ADJ_ELEMS (B_*14*N_*N_)      // 117,440,512

// ---------------- scratch (static device globals; no allocs) ----------------
__device__ float g_x  [B_*N_*HID];
__device__ float g_h  [B_*N_*C_];
__device__ float g_o1 [B_*N_*C_];
__device__ float g_src[B_*H_*N_];
__device__ float g_dst[B_*H_*N_];
__device__ float g_m  [B_*H_*N_];
__device__ float g_rz [B_*H_*N_];

#define FMA4(acc, s, v) { acc.x += (s)*(v).x; acc.y += (s)*(v).y; acc.z += (s)*(v).z; acc.w += (s)*(v).w; }

// ============================================================
// Kernel 1: adjacency. Positions of special pairs are data-independent;
// only shot-pair relation index reads shot_type.
// ============================================================
__device__ __forceinline__ float adj_val(int b, int r, int n, int m, const int* __restrict__ shot) {
    if (n == m) return 0.f;
    int p = n < m ? n : m;
    int q = n < m ? m : n;
    int d = q - p;
    int pm = p & 3;
    bool basep = (d == 2);                                       // every (p,p+2) is a base edge
    bool shotp = (d == 3 && pm == 0 && p <= 508) ||              // even step: (4k,4k+3)
                 (d == 1 && pm == 3 && p <= 507);                // odd step:  (4k+3,4k+4)
    if (r == 13) return (!basep && !shotp) ? 1.f : 0.f;
    if (r >= 11) {
        int rel = (pm == 0 || pm == 3) ? 11 : 12;
        return (basep && rel == r) ? 1.f : 0.f;
    }
    if (shotp) {
        int s = p >> 1;                                          // works for both parities
        return (shot[b * S_ + s] == r) ? 1.f : 0.f;
    }
    return 0.f;
}

__global__ void adj_kernel(const int* __restrict__ shot, float* __restrict__ out) {
    long long idx = (long long)blockIdx.x * blockDim.x + threadIdx.x;  // one float4 group
    int m0 = (int)(idx & 127) << 2;
    int n  = (int)(idx >> 7) & 511;
    int br = (int)(idx >> 16);
    int r = br % 14;
    int b = br / 14;
    float4 v;
    v.x = adj_val(b, r, n, m0 + 0, shot);
    v.y = adj_val(b, r, n, m0 + 1, shot);
    v.z = adj_val(b, r, n, m0 + 2, shot);
    v.w = adj_val(b, r, n, m0 + 3, shot);
    reinterpret_cast<float4*>(out)[idx] = v;
}

// ============================================================
// Kernel 2: node features. x = concat(relu(coord@Wc+bc), emb[player]) @ Wm + bm
// ============================================================
__global__ void feat_kernel(const int* __restrict__ player,
                            const float* __restrict__ Ax, const float* __restrict__ Ay,
                            const float* __restrict__ Bx, const float* __restrict__ By,
                            const float* __restrict__ emb,
                            const float* __restrict__ Wc, const float* __restrict__ bc,
                            const float* __restrict__ Wm, const float* __restrict__ bm,
                            float* __restrict__ x) {
    __shared__ float feat[32][64];
    __shared__ float wms[64 * 64];
    int blk = blockIdx.x;
    int b = blk >> 4;
    int n0 = (blk & 15) * 32;
    int tid = threadIdx.x;

    #pragma unroll
    for (int it = 0; it < 16; it++) wms[it * 256 + tid] = Wm[it * 256 + tid];

    #pragma unroll
    for (int it = 0; it < 8; it++) {
        int o = it * 256 + tid;
        int nl = o >> 6, c = o & 63;
        int n = n0 + nl;
        int e = n >> 1;
        float val;
        if (c < 32) {
            float cx, cy;
            if ((n & 1) == 0) { cx = Ax[b * E_ + e]; cy = Ay[b * E_ + e]; }
            else              { cx = Bx[b * E_ + e]; cy = By[b * E_ + e]; }
            val = fmaxf(cx * Wc[c] + cy * Wc[32 + c] + bc[c], 0.f);
        } else {
            int pid = player[b * 2 + (n & 1)];
            val = emb[pid * 32 + (c - 32)];
        }
        feat[nl][c] = val;
    }
    __syncthreads();

    #pragma unroll
    for (int it = 0; it < 8; it++) {
        int o = it * 256 + tid;
        int nl = o >> 6, k = o & 63;
        float acc = bm[k];
        #pragma unroll
        for (int c = 0; c < 64; c++) acc += feat[nl][c] * wms[c * 64 + k];
        x[(b * N_ + n0 + nl) * HID + k] = acc;
    }
}

// ============================================================
// Kernel 3: SGEMM  C[M,Kout] = A[M,KIN] @ W[KIN,Kout].
// 128x64 tile, 8x4 per thread, 256 threads.
// ============================================================
template<int KIN>
__global__ void gemm_kernel(const float* __restrict__ A, const float* __restrict__ W,
                            float* __restrict__ C, int Kout) {
    __shared__ float As[16][132];      // transposed A tile, padded
    __shared__ float Ws[16][64];
    int tid = threadIdx.x;
    int mt = blockIdx.y * 128, nt = blockIdx.x * 64;
    int fi = tid & 15, ii = tid >> 4;  // compute mapping: cols fi*4, rows ii*8

    int lr = tid >> 2;                 // A load: row 0..63 (+64 second half)
    int lk = (tid & 3) * 4;            // k group
    int wr = tid >> 4;                 // W load: k row 0..15
    int wc = (tid & 15) * 4;           // col group

    float4 acc[8];
    #pragma unroll
    for (int r = 0; r < 8; r++) acc[r] = make_float4(0.f, 0.f, 0.f, 0.f);

    for (int kt = 0; kt < KIN; kt += 16) {
        #pragma unroll
        for (int half = 0; half < 2; half++) {
            int row = lr + half * 64;
            float4 a = *reinterpret_cast<const float4*>(&A[(long long)(mt + row) * KIN + kt + lk]);
            As[lk + 0][row] = a.x; As[lk + 1][row] = a.y;
            As[lk + 2][row] = a.z; As[lk + 3][row] = a.w;
        }
        *reinterpret_cast<float4*>(&Ws[wr][wc]) =
            *reinterpret_cast<const float4*>(&W[(long long)(kt + wr) * Kout + nt + wc]);
        __syncthreads();
        #pragma unroll
        for (int k = 0; k < 16; k++) {
            float4 av0 = *reinterpret_cast<const float4*>(&As[k][ii * 8]);
            float4 av1 = *reinterpret_cast<const float4*>(&As[k][ii * 8 + 4]);
            float4 bv  = *reinterpret_cast<const float4*>(&Ws[k][fi * 4]);
            FMA4(acc[0], av0.x, bv); FMA4(acc[1], av0.y, bv);
            FMA4(acc[2], av0.z, bv); FMA4(acc[3], av0.w, bv);
            FMA4(acc[4], av1.x, bv); FMA4(acc[5], av1.y, bv);
            FMA4(acc[6], av1.z, bv); FMA4(acc[7], av1.w, bv);
        }
        __syncthreads();
    }
    #pragma unroll
    for (int r = 0; r < 8; r++) {
        long long base = (long long)(mt + ii * 8 + r) * Kout + nt + fi * 4;
        *reinterpret_cast<float4*>(&C[base]) = acc[r];
    }
}

// ============================================================
// Kernel 4: attention scores s_src/s_dst per (b,h,n).
// ============================================================
__global__ void score_kernel(const float* __restrict__ h, const float* __restrict__ att,
                             float* __restrict__ ssrc, float* __restrict__ sdst) {
    int bn = blockIdx.x;
    int b = bn >> 9, n = bn & 511;
    int c = threadIdx.x;
    int head = c >> 6, f = c & 63;
    float v = h[(long long)bn * C_ + c];
    float as = v * att[head * 128 + f];
    float ad = v * att[head * 128 + 64 + f];
    #pragma unroll
    for (int off = 16; off >= 1; off >>= 1) {
        as += __shfl_down_sync(0xffffffffu, as, off);
        ad += __shfl_down_sync(0xffffffffu, ad, off);
    }
    __shared__ float pS[8], pD[8];
    int w = c >> 5, lane = c & 31;
    if (lane == 0) { pS[w] = as; pD[w] = ad; }
    __syncthreads();
    if (c < 4) {
        ssrc[(b * H_ + c) * N_ + n] = pS[2 * c] + pS[2 * c + 1];
        sdst[(b * H_ + c) * N_ + n] = pD[2 * c] + pD[2 * c + 1];
    }
}

// ============================================================
// Kernel 5: softmax stats (max, 1/sum) per (b,h,i) over j != i.
// ============================================================
__global__ void mz_kernel(const float* __restrict__ ssrc, const float* __restrict__ sdst,
                          float* __restrict__ gm, float* __restrict__ grz) {
    int bh = blockIdx.x;
    __shared__ float sd[N_];
    int i = threadIdx.x;
    sd[i] = sdst[bh * N_ + i];
    __syncthreads();
    float a = ssrc[bh * N_ + i];
    float m = -1e30f;
    for (int j = 0; j < N_; j++) {
        if (j == i) continue;
        float v = a + sd[j];
        v = v > 0.f ? v : 0.2f * v;
        m = fmaxf(m, v);
    }
    float z = 0.f;
    for (int j = 0; j < N_; j++) {
        if (j == i) continue;
        float v = a + sd[j];
        v = v > 0.f ? v : 0.2f * v;
        z += __expf(v - m);
    }
    gm[bh * N_ + i] = m;
    grz[bh * N_ + i] = 1.f / z;
}

// ============================================================
// Kernel 6: aggregation out[b,i,c] = sum_j w_{h(c)}(i,j) h[b,j,c]
// One block: i-tile 64 x all 256 channels (4 heads). 256 thr, 8x8 reg tile.
// c-tile split as fi*4 / fi*4+128 => conflict-free LDS.128 on h;
// w loads are warp-broadcast.
// ============================================================
#define JB 16
__global__ void agg_kernel(const float* __restrict__ h,
                           const float* __restrict__ ssrc, const float* __restrict__ sdst,
                           const float* __restrict__ gm, const float* __restrict__ grz,
                           float* __restrict__ out, int dorelu) {
    int b = blockIdx.y;
    int i0 = blockIdx.x * 64;
    __shared__ float hjs[JB][256];
    __shared__ float wT[H_][JB][64];
    __shared__ float aS[H_][64], mS[H_][64], rS[H_][64];
    __shared__ float bj[H_][JB];

    int tid = threadIdx.x;
    {   // per-i stats: 4 heads x 64 i
        int hd = tid >> 6, i = tid & 63;
        int idx = (b * H_ + hd) * N_ + i0 + i;
        aS[hd][i] = ssrc[idx];
        mS[hd][i] = gm[idx];
        rS[hd][i] = grz[idx];
    }

    int fi = tid & 31, ii = tid >> 5;
    int headA = fi >> 4;           // c in [0,128): heads 0,1
    int headB = headA + 2;         // c in [128,256): heads 2,3
    int cA = fi * 4;
    int cB = cA + 128;

    float4 accA[8], accB[8];
    #pragma unroll
    for (int r = 0; r < 8; r++) {
        accA[r] = make_float4(0.f, 0.f, 0.f, 0.f);
        accB[r] = make_float4(0.f, 0.f, 0.f, 0.f);
    }

    for (int jb = 0; jb < N_; jb += JB) {
        __syncthreads();   // protect prev-iter smem reads + initial stats
        if (tid < H_ * JB) {
            int hd = tid >> 4, j = tid & (JB - 1);
            bj[hd][j] = sdst[(b * H_ + hd) * N_ + jb + j];
        }
        #pragma unroll
        for (int it = 0; it < 4; it++) {           // 16 j * 64 float4 = 1024
            int o = it * 256 + tid;
            int j = o >> 6, c4 = o & 63;
            reinterpret_cast<float4*>(&hjs[j][0])[c4] =
                reinterpret_cast<const float4*>(&h[(long long)(b * N_ + jb + j) * C_])[c4];
        }
        __syncthreads();
        {   // weights: thread (hd, i) over JB j's
            int hd = tid >> 6, i = tid & 63;
            float a = aS[hd][i], m = mS[hd][i], rz = rS[hd][i];
            int ig = i0 + i;
            #pragma unroll
            for (int j = 0; j < JB; j++) {
                float v = a + bj[hd][j];
                v = v > 0.f ? v : 0.2f * v;
                wT[hd][j][i] = (ig == jb + j) ? 0.f : __expf(v - m) * rz;
            }
        }
        __syncthreads();
        #pragma unroll
        for (int j = 0; j < JB; j++) {
            float4 hvA = *reinterpret_cast<const float4*>(&hjs[j][cA]);
            float4 hvB = *reinterpret_cast<const float4*>(&hjs[j][cB]);
            float4 wA0 = *reinterpret_cast<const float4*>(&wT[headA][j][ii * 8]);
            float4 wA1 = *reinterpret_cast<const float4*>(&wT[headA][j][ii * 8 + 4]);
            float4 wB0 = *reinterpret_cast<const float4*>(&wT[headB][j][ii * 8]);
            float4 wB1 = *reinterpret_cast<const float4*>(&wT[headB][j][ii * 8 + 4]);
            FMA4(accA[0], wA0.x, hvA); FMA4(accA[1], wA0.y, hvA);
            FMA4(accA[2], wA0.z, hvA); FMA4(accA[3], wA0.w, hvA);
            FMA4(accA[4], wA1.x, hvA); FMA4(accA[5], wA1.y, hvA);
            FMA4(accA[6], wA1.z, hvA); FMA4(accA[7], wA1.w, hvA);
            FMA4(accB[0], wB0.x, hvB); FMA4(accB[1], wB0.y, hvB);
            FMA4(accB[2], wB0.z, hvB); FMA4(accB[3], wB0.w, hvB);
            FMA4(accB[4], wB1.x, hvB); FMA4(accB[5], wB1.y, hvB);
            FMA4(accB[6], wB1.z, hvB); FMA4(accB[7], wB1.w, hvB);
        }
    }

    #pragma unroll
    for (int r = 0; r < 8; r++) {
        int row = i0 + ii * 8 + r;
        float4 va = accA[r], vb = accB[r];
        if (dorelu) {
            va.x = fmaxf(va.x, 0.f); va.y = fmaxf(va.y, 0.f);
            va.z = fmaxf(va.z, 0.f); va.w = fmaxf(va.w, 0.f);
            vb.x = fmaxf(vb.x, 0.f); vb.y = fmaxf(vb.y, 0.f);
            vb.z = fmaxf(vb.z, 0.f); vb.w = fmaxf(vb.w, 0.f);
        }
        long long base = (long long)(b * N_ + row) * C_;
        *reinterpret_cast<float4*>(&out[base + cA]) = va;
        *reinterpret_cast<float4*>(&out[base + cB]) = vb;
    }
}

// ============================================================
// launch
// ============================================================
extern "C" void kernel_launch(void* const* d_in, const int* in_sizes, int n_in,
                              void* d_out, int out_size) {
    int off = (n_in >= 16) ? 1 : 0;
    const int*   player = (const int*)  d_in[0];
    const int*   shot   = (const int*)  d_in[1];
    const float* Ax     = (const float*)d_in[2];
    const float* Ay     = (const float*)d_in[3];
    const float* Bx     = (const float*)d_in[4];
    const float* By     = (const float*)d_in[5];
    const float* emb    = (const float*)d_in[6 + off];
    const float* Wc     = (const float*)d_in[7 + off];
    const float* bc     = (const float*)d_in[8 + off];
    const float* Wm     = (const float*)d_in[9 + off];
    const float* bm     = (const float*)d_in[10 + off];
    const float* lin1   = (const float*)d_in[11 + off];
    const float* att1   = (const float*)d_in[12 + off];
    const float* lin2   = (const float*)d_in[13 + off];
    const float* att2   = (const float*)d_in[14 + off];

    float* out_ne  = (float*)d_out;
    float* out_adj = out_ne + NE_ELEMS;

    float *px, *ph, *po1, *psrc, *pdst, *pm, *prz;
    cudaGetSymbolAddress((void**)&px,  g_x);
    cudaGetSymbolAddress((void**)&ph,  g_h);
    cudaGetSymbolAddress((void**)&po1, g_o1);
    cudaGetSymbolAddress((void**)&psrc, g_src);
    cudaGetSymbolAddress((void**)&pdst, g_dst);
    cudaGetSymbolAddress((void**)&pm,  g_m);
    cudaGetSymbolAddress((void**)&prz, g_rz);

    if (out_size >= NE_ELEMS + ADJ_ELEMS) {
        adj_kernel<<<ADJ_ELEMS / 4 / 256, 256>>>(shot, out_adj);
    }

    feat_kernel<<<B_ * 16, 256>>>(player, Ax, Ay, Bx, By, emb, Wc, bc, Wm, bm, px);

    dim3 ggrid(C_ / 64, (B_ * N_) / 128);
    dim3 agrid(N_ / 64, B_);

    // ---- layer 1 ----
    gemm_kernel<HID><<<ggrid, 256>>>(px, lin1, ph, C_);
    score_kernel<<<B_ * N_, 256>>>(ph, att1, psrc, pdst);
    mz_kernel<<<B_ * H_, N_>>>(psrc, pdst, pm, prz);
    agg_kernel<<<agrid, 256>>>(ph, psrc, pdst, pm, prz, po1, 1);

    // ---- layer 2 ----
    gemm_kernel<C_><<<ggrid, 256>>>(po1, lin2, ph, C_);
    score_kernel<<<B_ * N_, 256>>>(ph, att2, psrc, pdst);
    mz_kernel<<<B_ * H_, N_>>>(psrc, pdst, pm, prz);
    agg_kernel<<<agrid, 256>>>(ph, psrc, pdst, pm, prz, out_ne, 0);
}

// round 3
// speedup vs baseline: 1.3501x; 1.3501x over previous
#include <cuda_runtime.h>

// ---------------- problem constants (fixed shapes) ----------------
#define B_    32
#define E_    256
#define N_    512          // 2E nodes
#define HID   64           // hidden
#define H_    4            // heads
#define F_    64           // per-head feature
#define C_    256          // H*F
#define S_    255          // E-1 shot steps
#define BH_   (B_*H_)
#define NE_ELEMS (B_*N_*C_)          // 4,194,304
#define ADJ_ELEMS (B_*14*N_*N_)      // 117,440,512

// ---------------- scratch (static device globals; no allocs) ----------------
__device__ float g_x  [B_*N_*HID];
__device__ float g_h  [B_*N_*C_];
__device__ float g_o1 [B_*N_*C_];
__device__ float g_src[BH_*N_];
__device__ float g_dst[BH_*N_];
// factorized-softmax scratch
__device__ int   g_sidx[BH_*N_];
__device__ float g_e1 [BH_*N_];
__device__ float g_e2 [BH_*N_];
__device__ int   g_t  [BH_*N_];
__device__ float g_c1 [BH_*N_];
__device__ float g_c2 [BH_*N_];
__device__ float g_ns [BH_*N_];
__device__ float g_V1 [BH_*(N_+1)*F_];
__device__ float g_V2 [BH_*(N_+1)*F_];

#define FMA4(acc, s, v) { acc.x += (s)*(v).x; acc.y += (s)*(v).y; acc.z += (s)*(v).z; acc.w += (s)*(v).w; }

// ============================================================
// Kernel 1a: adjacency static fill. 32 elements (8 x float4) per thread.
// r<11: zeros. r=11/12: zeros + <=2 base-pair patches per row.
// r=13: ones except band [n-3,n+3] exceptions.
// ============================================================
__global__ void fill_kernel(float* __restrict__ out) {
    int t = threadIdx.x;
    int n  = blockIdx.x * 16 + (t >> 4);
    int m0 = (t & 15) * 32;
    int r = blockIdx.y, b = blockIdx.z;
    float* p = out + ((((long long)b * 14 + r) * N_ + n) << 9) + m0;
    float4* p4 = reinterpret_cast<float4*>(p);

    if (r < 13) {
        float4 z = make_float4(0.f, 0.f, 0.f, 0.f);
        #pragma unroll
        for (int q = 0; q < 8; q++) __stcs(p4 + q, z);
        if (r >= 11) {
            // base-pair patches: columns n+2 (p0=n) and n-2 (p0=n-2)
            int cu = n + 2;
            if (cu < N_ && cu >= m0 && cu < m0 + 32) {
                int rel = ((n & 3) == 0 || (n & 3) == 3) ? 11 : 12;
                if (rel == r) p[cu - m0] = 1.f;
            }
            int cd = n - 2;
            if (cd >= 0 && cd >= m0 && cd < m0 + 32) {
                int pp = n - 2;
                int rel = ((pp & 3) == 0 || (pp & 3) == 3) ? 11 : 12;
                if (rel == r) p[cd - m0] = 1.f;
            }
        }
        return;
    }
    // r == 13: exceptions only within [n-3, n+3]
    if (n + 3 < m0 || n - 3 >= m0 + 32) {
        float4 o1 = make_float4(1.f, 1.f, 1.f, 1.f);
        #pragma unroll
        for (int q = 0; q < 8; q++) __stcs(p4 + q, o1);
        return;
    }
    int sp1 = -1, sp2 = -1;
    int nm = n & 3;
    if (nm == 0) {                  // shot partners of even-class rows
        if (n <= 508) sp1 = n + 3;  // (n, n+3), p=n
        if (n >= 4)   sp2 = n - 1;  // (n-1, n), p=n-1 (<=507 automatic)
    } else if (nm == 3) {
        if (n <= 507) sp1 = n + 1;  // (n, n+1), p=n
        sp2 = n - 3;                // (n-3, n), p=n-3
    }
    float vals[32];
    #pragma unroll
    for (int q = 0; q < 32; q++) {
        int m = m0 + q;
        bool zero = (m == n) | (m == n - 2) | (m == n + 2) | (m == sp1) | (m == sp2);
        vals[q] = zero ? 0.f : 1.f;
    }
    #pragma unroll
    for (int q = 0; q < 8; q++)
        __stcs(p4 + q, make_float4(vals[4*q], vals[4*q+1], vals[4*q+2], vals[4*q+3]));
}

// ============================================================
// Kernel 1b: scatter shot edges into their relation slice.
// ============================================================
__global__ void scatter_kernel(const int* __restrict__ shot, float* __restrict__ out) {
    int idx = blockIdx.x * 256 + threadIdx.x;
    if (idx >= B_ * S_) return;
    int b = idx / S_, s = idx % S_;
    int r = shot[idx];
    int i, j;
    if ((s & 1) == 0) { i = 2 * s;     j = 2 * s + 3; }
    else              { i = 2 * s + 1; j = 2 * s + 2; }
    long long base = ((long long)b * 14 + r) * (N_ * N_);
    out[base + (long long)i * N_ + j] = 1.f;
    out[base + (long long)j * N_ + i] = 1.f;
}

// ============================================================
// Kernel 2: node features. x = concat(relu(coord@Wc+bc), emb[player]) @ Wm + bm
// ============================================================
__global__ void feat_kernel(const int* __restrict__ player,
                            const float* __restrict__ Ax, const float* __restrict__ Ay,
                            const float* __restrict__ Bx, const float* __restrict__ By,
                            const float* __restrict__ emb,
                            const float* __restrict__ Wc, const float* __restrict__ bc,
                            const float* __restrict__ Wm, const float* __restrict__ bm,
                            float* __restrict__ x) {
    __shared__ float feat[32][64];
    __shared__ float wms[64 * 64];
    int blk = blockIdx.x;
    int b = blk >> 4;
    int n0 = (blk & 15) * 32;
    int tid = threadIdx.x;

    #pragma unroll
    for (int it = 0; it < 16; it++) wms[it * 256 + tid] = Wm[it * 256 + tid];

    #pragma unroll
    for (int it = 0; it < 8; it++) {
        int o = it * 256 + tid;
        int nl = o >> 6, c = o & 63;
        int n = n0 + nl;
        int e = n >> 1;
        float val;
        if (c < 32) {
            float cx, cy;
            if ((n & 1) == 0) { cx = Ax[b * E_ + e]; cy = Ay[b * E_ + e]; }
            else              { cx = Bx[b * E_ + e]; cy = By[b * E_ + e]; }
            val = fmaxf(cx * Wc[c] + cy * Wc[32 + c] + bc[c], 0.f);
        } else {
            int pid = player[b * 2 + (n & 1)];
            val = emb[pid * 32 + (c - 32)];
        }
        feat[nl][c] = val;
    }
    __syncthreads();

    #pragma unroll
    for (int it = 0; it < 8; it++) {
        int o = it * 256 + tid;
        int nl = o >> 6, k = o & 63;
        float acc = bm[k];
        #pragma unroll
        for (int c = 0; c < 64; c++) acc += feat[nl][c] * wms[c * 64 + k];
        x[(b * N_ + n0 + nl) * HID + k] = acc;
    }
}

// ============================================================
// Kernel 3: SGEMM  C[M,Kout] = A[M,KIN] @ W[KIN,Kout]. 128x64 tile, 8x4/thread.
// ============================================================
template<int KIN>
__global__ void gemm_kernel(const float* __restrict__ A, const float* __restrict__ W,
                            float* __restrict__ C, int Kout) {
    __shared__ float As[16][132];
    __shared__ float Ws[16][64];
    int tid = threadIdx.x;
    int mt = blockIdx.y * 128, nt = blockIdx.x * 64;
    int fi = tid & 15, ii = tid >> 4;
    int lr = tid >> 2;
    int lk = (tid & 3) * 4;
    int wr = tid >> 4;
    int wc = (tid & 15) * 4;

    float4 acc[8];
    #pragma unroll
    for (int r = 0; r < 8; r++) acc[r] = make_float4(0.f, 0.f, 0.f, 0.f);

    for (int kt = 0; kt < KIN; kt += 16) {
        #pragma unroll
        for (int half = 0; half < 2; half++) {
            int row = lr + half * 64;
            float4 a = *reinterpret_cast<const float4*>(&A[(long long)(mt + row) * KIN + kt + lk]);
            As[lk + 0][row] = a.x; As[lk + 1][row] = a.y;
            As[lk + 2][row] = a.z; As[lk + 3][row] = a.w;
        }
        *reinterpret_cast<float4*>(&Ws[wr][wc]) =
            *reinterpret_cast<const float4*>(&W[(long long)(kt + wr) * Kout + nt + wc]);
        __syncthreads();
        #pragma unroll
        for (int k = 0; k < 16; k++) {
            float4 av0 = *reinterpret_cast<const float4*>(&As[k][ii * 8]);
            float4 av1 = *reinterpret_cast<const float4*>(&As[k][ii * 8 + 4]);
            float4 bv  = *reinterpret_cast<const float4*>(&Ws[k][fi * 4]);
            FMA4(acc[0], av0.x, bv); FMA4(acc[1], av0.y, bv);
            FMA4(acc[2], av0.z, bv); FMA4(acc[3], av0.w, bv);
            FMA4(acc[4], av1.x, bv); FMA4(acc[5], av1.y, bv);
            FMA4(acc[6], av1.z, bv); FMA4(acc[7], av1.w, bv);
        }
        __syncthreads();
    }
    #pragma unroll
    for (int r = 0; r < 8; r++) {
        long long base = (long long)(mt + ii * 8 + r) * Kout + nt + fi * 4;
        *reinterpret_cast<float4*>(&C[base]) = acc[r];
    }
}

// ============================================================
// Kernel 4: attention scores a=s_src, b=s_dst per (b,h,n).
// ============================================================
__global__ void score_kernel(const float* __restrict__ h, const float* __restrict__ att,
                             float* __restrict__ ssrc, float* __restrict__ sdst) {
    int bn = blockIdx.x;
    int b = bn >> 9, n = bn & 511;
    int c = threadIdx.x;
    int head = c >> 6, f = c & 63;
    float v = h[(long long)bn * C_ + c];
    float as = v * att[head * 128 + f];
    float ad = v * att[head * 128 + 64 + f];
    #pragma unroll
    for (int off = 16; off >= 1; off >>= 1) {
        as += __shfl_down_sync(0xffffffffu, as, off);
        ad += __shfl_down_sync(0xffffffffu, ad, off);
    }
    __shared__ float pS[8], pD[8];
    int w = c >> 5, lane = c & 31;
    if (lane == 0) { pS[w] = as; pD[w] = ad; }
    __syncthreads();
    if (c < 4) {
        ssrc[(b * H_ + c) * N_ + n] = pS[2 * c] + pS[2 * c + 1];
        sdst[(b * H_ + c) * N_ + n] = pD[2 * c] + pD[2 * c + 1];
    }
}

// ============================================================
// Kernel 5a: per (b,h): sort b_j, scalar scans, per-i threshold/coeffs.
// Factorization: score(i,j) = a_i + b_j (rank-1). LeakyReLU kink splits j
// at b_j > -a_i, a contiguous suffix in sorted order.
// ============================================================
__global__ void sortscan_kernel(const float* __restrict__ ssrc, const float* __restrict__ sdst,
                                int* __restrict__ sidx_g, float* __restrict__ e1_g,
                                float* __restrict__ e2_g, int* __restrict__ t_g,
                                float* __restrict__ c1_g, float* __restrict__ c2_g,
                                float* __restrict__ ns_g) {
    int bh = blockIdx.x;
    int i = threadIdx.x;
    __shared__ float sv[N_];
    __shared__ int   si[N_];
    __shared__ float se1[N_], se2[N_];
    __shared__ float sP1[N_ + 1], sP2[N_ + 1];
    __shared__ float sbuf[N_];

    float bval = sdst[bh * N_ + i];
    // block max of b
    sbuf[i] = bval; __syncthreads();
    #pragma unroll
    for (int o = 256; o > 0; o >>= 1) {
        if (i < o) sbuf[i] = fmaxf(sbuf[i], sbuf[i + o]);
        __syncthreads();
    }
    float mb = sbuf[0];
    __syncthreads();

    sv[i] = bval - mb; si[i] = i;
    __syncthreads();
    // bitonic sort ascending (value, index)
    for (int k = 2; k <= N_; k <<= 1) {
        for (int j = k >> 1; j > 0; j >>= 1) {
            int l = i ^ j;
            if (l > i) {
                bool up = ((i & k) == 0);
                float v0 = sv[i], v1 = sv[l];
                if ((v0 > v1) == up) {
                    sv[i] = v1; sv[l] = v0;
                    int t0 = si[i]; si[i] = si[l]; si[l] = t0;
                }
            }
            __syncthreads();
        }
    }

    float e1 = __expf(sv[i]);
    float e2 = __expf(0.2f * sv[i]);
    se1[i] = e1; se2[i] = e2;

    // P2: exclusive prefix of e2
    sbuf[i] = e2; __syncthreads();
    for (int o = 1; o < N_; o <<= 1) {
        float v = sbuf[i];
        if (i >= o) v += sbuf[i - o];
        __syncthreads();
        sbuf[i] = v;
        __syncthreads();
    }
    sP2[i + 1] = sbuf[i];
    if (i == 0) sP2[0] = 0.f;
    __syncthreads();
    // P1: inclusive suffix of e1
    sbuf[i] = e1; __syncthreads();
    for (int o = 1; o < N_; o <<= 1) {
        float v = sbuf[i];
        if (i + o < N_) v += sbuf[i + o];
        __syncthreads();
        sbuf[i] = v;
        __syncthreads();
    }
    sP1[i] = sbuf[i];
    if (i == 0) sP1[N_] = 0.f;
    __syncthreads();

    // persist sorted arrays for the vector scan
    sidx_g[bh * N_ + i] = si[i];
    e1_g[bh * N_ + i] = se1[i];
    e2_g[bh * N_ + i] = se2[i];

    // per-i coefficients
    float a = ssrc[bh * N_ + i];
    float thr = -a - mb;                       // positive branch iff beta > thr
    int lo = 0, hi = N_;
    while (lo < hi) {
        int mid = (lo + hi) >> 1;
        if (sv[mid] > thr) hi = mid; else lo = mid + 1;
    }
    int t = lo;
    float s = a + mb;
    float m = s > 0.f ? s : 0.2f * s;          // m_i = leaky(a_i + max_b)
    float c1v = __expf(s - m);
    float c2v = __expf(0.2f * s - m);
    float sci = a + bval;
    float lsci = sci > 0.f ? sci : 0.2f * sci;
    float ns = __expf(lsci - m);               // self weight (unnormalized)
    float Z = c1v * sP1[t] + c2v * sP2[t] - ns;
    float rz = 1.f / fmaxf(Z, 1e-35f);
    t_g [bh * N_ + i] = t;
    c1_g[bh * N_ + i] = c1v * rz;
    c2_g[bh * N_ + i] = c2v * rz;
    ns_g[bh * N_ + i] = ns * rz;
}

// ============================================================
// Kernel 5b: vector scans V1 (suffix, e1*h) and V2 (exclusive prefix, e2*h).
// One block of 64 lanes per (b,h).
// ============================================================
__global__ void vscan_kernel(const float* __restrict__ h,
                             const int* __restrict__ sidx_g,
                             const float* __restrict__ e1_g, const float* __restrict__ e2_g,
                             float* __restrict__ V1, float* __restrict__ V2) {
    int bh = blockIdx.x;
    int f = threadIdx.x;             // 64 lanes
    int b = bh >> 2, hd = bh & 3;
    const float* hb = h + (long long)b * N_ * C_ + hd * 64 + f;
    float* v1p = V1 + ((long long)bh * (N_ + 1)) * F_ + f;
    float* v2p = V2 + ((long long)bh * (N_ + 1)) * F_ + f;
    const int* sidx = sidx_g + bh * N_;
    const float* e1 = e1_g + bh * N_;
    const float* e2 = e2_g + bh * N_;

    float acc = 0.f;
    #pragma unroll 4
    for (int k = 0; k < N_; k++) {
        v2p[(long long)k * F_] = acc;
        int j = sidx[k];
        acc += e2[k] * hb[(long long)j * C_];
    }
    v2p[(long long)N_ * F_] = acc;

    acc = 0.f;
    v1p[(long long)N_ * F_] = 0.f;
    #pragma unroll 4
    for (int k = N_ - 1; k >= 0; k--) {
        int j = sidx[k];
        acc += e1[k] * hb[(long long)j * C_];
        v1p[(long long)k * F_] = acc;
    }
}

// ============================================================
// Kernel 5c: emit out[b,i,hd*64+f] = c1*V1[t] + c2*V2[t] - ns*h_i (normalized).
// ============================================================
__global__ void emit_kernel(const float* __restrict__ h,
                            const float* __restrict__ V1, const float* __restrict__ V2,
                            const int* __restrict__ t_g, const float* __restrict__ c1_g,
                            const float* __restrict__ c2_g, const float* __restrict__ ns_g,
                            float* __restrict__ out, int dorelu) {
    int bh = blockIdx.y;
    int i = blockIdx.x * 4 + (threadIdx.x >> 6);
    int f = threadIdx.x & 63;
    int b = bh >> 2, hd = bh & 3;
    int idx = bh * N_ + i;
    int t = t_g[idx];
    float c1 = c1_g[idx], c2 = c2_g[idx], ns = ns_g[idx];
    long long hoff = ((long long)(b * N_ + i)) * C_ + hd * 64 + f;
    float hv = h[hoff];
    float v1 = V1[((long long)bh * (N_ + 1) + t) * F_ + f];
    float v2 = V2[((long long)bh * (N_ + 1) + t) * F_ + f];
    float o = c1 * v1 + c2 * v2 - ns * hv;
    if (dorelu) o = fmaxf(o, 0.f);
    out[hoff] = o;
}

// ============================================================
// launch
// ============================================================
extern "C" void kernel_launch(void* const* d_in, const int* in_sizes, int n_in,
                              void* d_out, int out_size) {
    int off = (n_in >= 16) ? 1 : 0;
    const int*   player = (const int*)  d_in[0];
    const int*   shot   = (const int*)  d_in[1];
    const float* Ax     = (const float*)d_in[2];
    const float* Ay     = (const float*)d_in[3];
    const float* Bx     = (const float*)d_in[4];
    const float* By     = (const float*)d_in[5];
    const float* emb    = (const float*)d_in[6 + off];
    const float* Wc     = (const float*)d_in[7 + off];
    const float* bc     = (const float*)d_in[8 + off];
    const float* Wm     = (const float*)d_in[9 + off];
    const float* bm     = (const float*)d_in[10 + off];
    const float* lin1   = (const float*)d_in[11 + off];
    const float* att1   = (const float*)d_in[12 + off];
    const float* lin2   = (const float*)d_in[13 + off];
    const float* att2   = (const float*)d_in[14 + off];

    float* out_ne  = (float*)d_out;
    float* out_adj = out_ne + NE_ELEMS;

    float *px, *ph, *po1, *psrc, *pdst;
    float *pe1, *pe2, *pc1, *pc2, *pns, *pV1, *pV2;
    int *psidx, *pt;
    cudaGetSymbolAddress((void**)&px,  g_x);
    cudaGetSymbolAddress((void**)&ph,  g_h);
    cudaGetSymbolAddress((void**)&po1, g_o1);
    cudaGetSymbolAddress((void**)&psrc, g_src);
    cudaGetSymbolAddress((void**)&pdst, g_dst);
    cudaGetSymbolAddress((void**)&psidx, g_sidx);
    cudaGetSymbolAddress((void**)&pe1, g_e1);
    cudaGetSymbolAddress((void**)&pe2, g_e2);
    cudaGetSymbolAddress((void**)&pt,  g_t);
    cudaGetSymbolAddress((void**)&pc1, g_c1);
    cudaGetSymbolAddress((void**)&pc2, g_c2);
    cudaGetSymbolAddress((void**)&pns, g_ns);
    cudaGetSymbolAddress((void**)&pV1, g_V1);
    cudaGetSymbolAddress((void**)&pV2, g_V2);

    if (out_size >= NE_ELEMS + ADJ_ELEMS) {
        fill_kernel<<<dim3(N_ / 16, 14, B_), 256>>>(out_adj);
        scatter_kernel<<<(B_ * S_ + 255) / 256, 256>>>(shot, out_adj);
    }

    feat_kernel<<<B_ * 16, 256>>>(player, Ax, Ay, Bx, By, emb, Wc, bc, Wm, bm, px);

    dim3 ggrid(C_ / 64, (B_ * N_) / 128);
    dim3 egrid(N_ / 4, BH_);

    // ---- layer 1 ----
    gemm_kernel<HID><<<ggrid, 256>>>(px, lin1, ph, C_);
    score_kernel<<<B_ * N_, 256>>>(ph, att1, psrc, pdst);
    sortscan_kernel<<<BH_, N_>>>(psrc, pdst, psidx, pe1, pe2, pt, pc1, pc2, pns);
    vscan_kernel<<<BH_, F_>>>(ph, psidx, pe1, pe2, pV1, pV2);
    emit_kernel<<<egrid, 256>>>(ph, pV1, pV2, pt, pc1, pc2, pns, po1, 1);

    // ---- layer 2 ----
    gemm_kernel<C_><<<ggrid, 256>>>(po1, lin2, ph, C_);
    score_kernel<<<B_ * N_, 256>>>(ph, att2, psrc, pdst);
    sortscan_kernel<<<BH_, N_>>>(psrc, pdst, psidx, pe1, pe2, pt, pc1, pc2, pns);
    vscan_kernel<<<BH_, F_>>>(ph, psidx, pe1, pe2, pV1, pV2);
    emit_kernel<<<egrid, 256>>>(ph, pV1, pV2, pt, pc1, pc2, pns, out_ne, 0);
}

// round 4
// speedup vs baseline: 1.6630x; 1.2317x over previous
#include <cuda_runtime.h>

// ---------------- problem constants (fixed shapes) ----------------
#define B_    32
#define E_    256
#define N_    512          // 2E nodes
#define HID   64           // hidden
#define H_    4            // heads
#define F_    64           // per-head feature
#define C_    256          // H*F
#define S_    255          // E-1 shot steps
#define BH_   (B_*H_)
#define NE_ELEMS (B_*N_*C_)          // 4,194,304
#define ADJ_ELEMS (B_*14*N_*N_)      // 117,440,512

// ---------------- scratch (static device globals; no allocs) ----------------
__device__ float g_x  [B_*N_*HID];
__device__ float g_h  [B_*N_*C_];
__device__ float g_o1 [B_*N_*C_];
__device__ float g_src[BH_*N_];
__device__ float g_dst[BH_*N_];
__device__ int   g_sidx[BH_*N_];
__device__ float g_e1 [BH_*N_];
__device__ float g_e2 [BH_*N_];
__device__ int   g_t  [BH_*N_];
__device__ float g_c1 [BH_*N_];
__device__ float g_c2 [BH_*N_];
__device__ float g_ns [BH_*N_];
__device__ float g_V1 [BH_*(N_+1)*F_];
__device__ float g_V2 [BH_*(N_+1)*F_];

#define FMA4(acc, s, v) { acc.x += (s)*(v).x; acc.y += (s)*(v).y; acc.z += (s)*(v).z; acc.w += (s)*(v).w; }

// ============================================================
// Kernel 1a: adjacency static fill. 32 elements (8 x float4) per thread.
// ============================================================
__global__ void fill_kernel(float* __restrict__ out) {
    int t = threadIdx.x;
    int n  = blockIdx.x * 16 + (t >> 4);
    int m0 = (t & 15) * 32;
    int r = blockIdx.y, b = blockIdx.z;
    float* p = out + ((((long long)b * 14 + r) * N_ + n) << 9) + m0;
    float4* p4 = reinterpret_cast<float4*>(p);

    if (r < 13) {
        float4 z = make_float4(0.f, 0.f, 0.f, 0.f);
        #pragma unroll
        for (int q = 0; q < 8; q++) __stcs(p4 + q, z);
        if (r >= 11) {
            int cu = n + 2;
            if (cu < N_ && cu >= m0 && cu < m0 + 32) {
                int rel = ((n & 3) == 0 || (n & 3) == 3) ? 11 : 12;
                if (rel == r) p[cu - m0] = 1.f;
            }
            int cd = n - 2;
            if (cd >= 0 && cd >= m0 && cd < m0 + 32) {
                int pp = n - 2;
                int rel = ((pp & 3) == 0 || (pp & 3) == 3) ? 11 : 12;
                if (rel == r) p[cd - m0] = 1.f;
            }
        }
        return;
    }
    if (n + 3 < m0 || n - 3 >= m0 + 32) {
        float4 o1 = make_float4(1.f, 1.f, 1.f, 1.f);
        #pragma unroll
        for (int q = 0; q < 8; q++) __stcs(p4 + q, o1);
        return;
    }
    int sp1 = -1, sp2 = -1;
    int nm = n & 3;
    if (nm == 0) {
        if (n <= 508) sp1 = n + 3;
        if (n >= 4)   sp2 = n - 1;
    } else if (nm == 3) {
        if (n <= 507) sp1 = n + 1;
        sp2 = n - 3;
    }
    float vals[32];
    #pragma unroll
    for (int q = 0; q < 32; q++) {
        int m = m0 + q;
        bool zero = (m == n) | (m == n - 2) | (m == n + 2) | (m == sp1) | (m == sp2);
        vals[q] = zero ? 0.f : 1.f;
    }
    #pragma unroll
    for (int q = 0; q < 8; q++)
        __stcs(p4 + q, make_float4(vals[4*q], vals[4*q+1], vals[4*q+2], vals[4*q+3]));
}

__global__ void scatter_kernel(const int* __restrict__ shot, float* __restrict__ out) {
    int idx = blockIdx.x * 256 + threadIdx.x;
    if (idx >= B_ * S_) return;
    int b = idx / S_, s = idx % S_;
    int r = shot[idx];
    int i, j;
    if ((s & 1) == 0) { i = 2 * s;     j = 2 * s + 3; }
    else              { i = 2 * s + 1; j = 2 * s + 2; }
    long long base = ((long long)b * 14 + r) * (N_ * N_);
    out[base + (long long)i * N_ + j] = 1.f;
    out[base + (long long)j * N_ + i] = 1.f;
}

// ============================================================
// Kernel 2: node features.
// ============================================================
__global__ void feat_kernel(const int* __restrict__ player,
                            const float* __restrict__ Ax, const float* __restrict__ Ay,
                            const float* __restrict__ Bx, const float* __restrict__ By,
                            const float* __restrict__ emb,
                            const float* __restrict__ Wc, const float* __restrict__ bc,
                            const float* __restrict__ Wm, const float* __restrict__ bm,
                            float* __restrict__ x) {
    __shared__ float feat[32][64];
    __shared__ float wms[64 * 64];
    int blk = blockIdx.x;
    int b = blk >> 4;
    int n0 = (blk & 15) * 32;
    int tid = threadIdx.x;

    #pragma unroll
    for (int it = 0; it < 16; it++) wms[it * 256 + tid] = Wm[it * 256 + tid];

    #pragma unroll
    for (int it = 0; it < 8; it++) {
        int o = it * 256 + tid;
        int nl = o >> 6, c = o & 63;
        int n = n0 + nl;
        int e = n >> 1;
        float val;
        if (c < 32) {
            float cx, cy;
            if ((n & 1) == 0) { cx = Ax[b * E_ + e]; cy = Ay[b * E_ + e]; }
            else              { cx = Bx[b * E_ + e]; cy = By[b * E_ + e]; }
            val = fmaxf(cx * Wc[c] + cy * Wc[32 + c] + bc[c], 0.f);
        } else {
            int pid = player[b * 2 + (n & 1)];
            val = emb[pid * 32 + (c - 32)];
        }
        feat[nl][c] = val;
    }
    __syncthreads();

    #pragma unroll
    for (int it = 0; it < 8; it++) {
        int o = it * 256 + tid;
        int nl = o >> 6, k = o & 63;
        float acc = bm[k];
        #pragma unroll
        for (int c = 0; c < 64; c++) acc += feat[nl][c] * wms[c * 64 + k];
        x[(b * N_ + n0 + nl) * HID + k] = acc;
    }
}

// ============================================================
// Kernel 3: SGEMM 128x128 tile, 8x8 per thread, 256 threads.
// C[M,256] = A[M,KIN] @ W[KIN,256]
// ============================================================
template<int KIN>
__global__ void gemm_kernel(const float* __restrict__ A, const float* __restrict__ W,
                            float* __restrict__ C) {
    __shared__ float As[8][132];
    __shared__ float Ws[8][128];
    const int Kout = C_;
    int tid = threadIdx.x;
    int mt = blockIdx.y * 128, nt = blockIdx.x * 128;
    int fi = tid & 15, ii = tid >> 4;

    int ar = tid >> 1;              // A load: row 0..127
    int ak = (tid & 1) * 4;         // k group
    int wr = tid >> 5;              // W load: k row 0..7
    int wc = (tid & 31) * 4;        // col group

    float4 acc[8][2];
    #pragma unroll
    for (int r = 0; r < 8; r++) {
        acc[r][0] = make_float4(0.f, 0.f, 0.f, 0.f);
        acc[r][1] = make_float4(0.f, 0.f, 0.f, 0.f);
    }

    for (int kt = 0; kt < KIN; kt += 8) {
        float4 a = *reinterpret_cast<const float4*>(&A[(long long)(mt + ar) * KIN + kt + ak]);
        As[ak + 0][ar] = a.x; As[ak + 1][ar] = a.y;
        As[ak + 2][ar] = a.z; As[ak + 3][ar] = a.w;
        *reinterpret_cast<float4*>(&Ws[wr][wc]) =
            *reinterpret_cast<const float4*>(&W[(long long)(kt + wr) * Kout + nt + wc]);
        __syncthreads();
        #pragma unroll
        for (int k = 0; k < 8; k++) {
            float4 av0 = *reinterpret_cast<const float4*>(&As[k][ii * 8]);
            float4 av1 = *reinterpret_cast<const float4*>(&As[k][ii * 8 + 4]);
            float4 bv0 = *reinterpret_cast<const float4*>(&Ws[k][fi * 8]);
            float4 bv1 = *reinterpret_cast<const float4*>(&Ws[k][fi * 8 + 4]);
            FMA4(acc[0][0], av0.x, bv0); FMA4(acc[0][1], av0.x, bv1);
            FMA4(acc[1][0], av0.y, bv0); FMA4(acc[1][1], av0.y, bv1);
            FMA4(acc[2][0], av0.z, bv0); FMA4(acc[2][1], av0.z, bv1);
            FMA4(acc[3][0], av0.w, bv0); FMA4(acc[3][1], av0.w, bv1);
            FMA4(acc[4][0], av1.x, bv0); FMA4(acc[4][1], av1.x, bv1);
            FMA4(acc[5][0], av1.y, bv0); FMA4(acc[5][1], av1.y, bv1);
            FMA4(acc[6][0], av1.z, bv0); FMA4(acc[6][1], av1.z, bv1);
            FMA4(acc[7][0], av1.w, bv0); FMA4(acc[7][1], av1.w, bv1);
        }
        __syncthreads();
    }
    #pragma unroll
    for (int r = 0; r < 8; r++) {
        long long base = (long long)(mt + ii * 8 + r) * Kout + nt + fi * 8;
        *reinterpret_cast<float4*>(&C[base])     = acc[r][0];
        *reinterpret_cast<float4*>(&C[base + 4]) = acc[r][1];
    }
}

// ============================================================
// Kernel 4: scores — one warp per (b,n,head).
// ============================================================
__global__ void score_kernel(const float* __restrict__ h, const float* __restrict__ att,
                             float* __restrict__ ssrc, float* __restrict__ sdst) {
    int gid = blockIdx.x * 8 + (threadIdx.x >> 5);
    int lane = threadIdx.x & 31;
    int bn = gid >> 2, head = gid & 3;
    int b = bn >> 9, n = bn & 511;
    float2 hv = *reinterpret_cast<const float2*>(&h[(long long)bn * C_ + head * 64 + lane * 2]);
    float2 a1 = *reinterpret_cast<const float2*>(&att[head * 128 + lane * 2]);
    float2 a2 = *reinterpret_cast<const float2*>(&att[head * 128 + 64 + lane * 2]);
    float as = hv.x * a1.x + hv.y * a1.y;
    float ad = hv.x * a2.x + hv.y * a2.y;
    #pragma unroll
    for (int off = 16; off >= 1; off >>= 1) {
        as += __shfl_down_sync(0xffffffffu, as, off);
        ad += __shfl_down_sync(0xffffffffu, ad, off);
    }
    if (lane == 0) {
        ssrc[(b * H_ + head) * N_ + n] = as;
        sdst[(b * H_ + head) * N_ + n] = ad;
    }
}

// ============================================================
// Kernel 5a: per (b,h): sort b_j, scalar scans, per-i threshold/coeffs.
// ============================================================
__global__ void sortscan_kernel(const float* __restrict__ ssrc, const float* __restrict__ sdst,
                                int* __restrict__ sidx_g, float* __restrict__ e1_g,
                                float* __restrict__ e2_g, int* __restrict__ t_g,
                                float* __restrict__ c1_g, float* __restrict__ c2_g,
                                float* __restrict__ ns_g) {
    int bh = blockIdx.x;
    int i = threadIdx.x;
    __shared__ float sv[N_];
    __shared__ int   si[N_];
    __shared__ float sP1[N_ + 1], sP2[N_ + 1];
    __shared__ float sbuf[N_];

    float bval = sdst[bh * N_ + i];
    sbuf[i] = bval; __syncthreads();
    #pragma unroll
    for (int o = 256; o > 0; o >>= 1) {
        if (i < o) sbuf[i] = fmaxf(sbuf[i], sbuf[i + o]);
        __syncthreads();
    }
    float mb = sbuf[0];
    __syncthreads();

    sv[i] = bval - mb; si[i] = i;
    __syncthreads();
    for (int k = 2; k <= N_; k <<= 1) {
        for (int j = k >> 1; j > 0; j >>= 1) {
            int l = i ^ j;
            if (l > i) {
                bool up = ((i & k) == 0);
                float v0 = sv[i], v1 = sv[l];
                if ((v0 > v1) == up) {
                    sv[i] = v1; sv[l] = v0;
                    int t0 = si[i]; si[i] = si[l]; si[l] = t0;
                }
            }
            __syncthreads();
        }
    }

    float e1 = __expf(sv[i]);
    float e2 = __expf(0.2f * sv[i]);

    sbuf[i] = e2; __syncthreads();
    for (int o = 1; o < N_; o <<= 1) {
        float v = sbuf[i];
        if (i >= o) v += sbuf[i - o];
        __syncthreads();
        sbuf[i] = v;
        __syncthreads();
    }
    sP2[i + 1] = sbuf[i];
    if (i == 0) sP2[0] = 0.f;
    __syncthreads();
    sbuf[i] = e1; __syncthreads();
    for (int o = 1; o < N_; o <<= 1) {
        float v = sbuf[i];
        if (i + o < N_) v += sbuf[i + o];
        __syncthreads();
        sbuf[i] = v;
        __syncthreads();
    }
    sP1[i] = sbuf[i];
    if (i == 0) sP1[N_] = 0.f;
    __syncthreads();

    sidx_g[bh * N_ + i] = si[i];
    e1_g[bh * N_ + i] = e1;
    e2_g[bh * N_ + i] = e2;

    float a = ssrc[bh * N_ + i];
    float thr = -a - mb;
    int lo = 0, hi = N_;
    while (lo < hi) {
        int mid = (lo + hi) >> 1;
        if (sv[mid] > thr) hi = mid; else lo = mid + 1;
    }
    int t = lo;
    float s = a + mb;
    float m = s > 0.f ? s : 0.2f * s;
    float c1v = __expf(s - m);
    float c2v = __expf(0.2f * s - m);
    float sci = a + bval;
    float lsci = sci > 0.f ? sci : 0.2f * sci;
    float ns = __expf(lsci - m);
    float Z = c1v * sP1[t] + c2v * sP2[t] - ns;
    float rz = 1.f / fmaxf(Z, 1e-35f);
    t_g [bh * N_ + i] = t;
    c1_g[bh * N_ + i] = c1v * rz;
    c2_g[bh * N_ + i] = c2v * rz;
    ns_g[bh * N_ + i] = ns * rz;
}

// ============================================================
// Kernel 5b: parallel vector scans. One block (512 thr) per (b,h).
// Whole sorted h-slice staged in smem (128KB); warp shfl scans over k
// (16 warps x 4 f each); coalesced stores via padded staging tile.
// ============================================================
__global__ void __launch_bounds__(512, 1)
vscan_kernel(const float* __restrict__ h,
             const int* __restrict__ sidx_g,
             const float* __restrict__ e1_g, const float* __restrict__ e2_g,
             float* __restrict__ V1, float* __restrict__ V2) {
    __shared__ float tile[N_][F_];      // 128 KB
    __shared__ float ob[32][65];        // staging, padded
    __shared__ float se1[N_], se2[N_];
    int bh = blockIdx.x;
    int b = bh >> 2, hd = bh & 3;
    int t = threadIdx.x;
    const int* sidx = sidx_g + bh * N_;
    const float* hb = h + (long long)b * N_ * C_ + hd * 64;

    se1[t] = e1_g[bh * N_ + t];
    se2[t] = e2_g[bh * N_ + t];
    // load sorted rows into smem (coalesced per row)
    #pragma unroll
    for (int it = 0; it < 16; it++) {
        int idx = it * 512 + t;
        int k = idx >> 4, q = idx & 15;
        *reinterpret_cast<float4*>(&tile[k][q * 4]) =
            *reinterpret_cast<const float4*>(&hb[(long long)sidx[k] * C_ + q * 4]);
    }
    __syncthreads();

    int w = t >> 5, l = t & 31;
    float* v1p = V1 + (long long)bh * (N_ + 1) * F_;
    float* v2p = V2 + (long long)bh * (N_ + 1) * F_;

    // ---- V2: exclusive prefix of e2*h ----
    float base0 = 0.f, base1 = 0.f, base2 = 0.f, base3 = 0.f;
    for (int c = 0; c < 16; c++) {
        int k = c * 32 + l;
        float ev = se2[k];
        float v0 = ev * tile[k][w * 4 + 0];
        float v1 = ev * tile[k][w * 4 + 1];
        float v2 = ev * tile[k][w * 4 + 2];
        float v3 = ev * tile[k][w * 4 + 3];
        float i0 = v0, i1 = v1, i2 = v2, i3 = v3;
        #pragma unroll
        for (int off = 1; off < 32; off <<= 1) {
            float n0 = __shfl_up_sync(0xffffffffu, i0, off);
            float n1 = __shfl_up_sync(0xffffffffu, i1, off);
            float n2 = __shfl_up_sync(0xffffffffu, i2, off);
            float n3 = __shfl_up_sync(0xffffffffu, i3, off);
            if (l >= off) { i0 += n0; i1 += n1; i2 += n2; i3 += n3; }
        }
        ob[l][w * 4 + 0] = base0 + i0 - v0;
        ob[l][w * 4 + 1] = base1 + i1 - v1;
        ob[l][w * 4 + 2] = base2 + i2 - v2;
        ob[l][w * 4 + 3] = base3 + i3 - v3;
        base0 += __shfl_sync(0xffffffffu, i0, 31);
        base1 += __shfl_sync(0xffffffffu, i1, 31);
        base2 += __shfl_sync(0xffffffffu, i2, 31);
        base3 += __shfl_sync(0xffffffffu, i3, 31);
        __syncthreads();
        {
            int kk = t >> 4, q = t & 15;
            float4 v = make_float4(ob[kk][q*4], ob[kk][q*4+1], ob[kk][q*4+2], ob[kk][q*4+3]);
            *reinterpret_cast<float4*>(&v2p[(long long)(c * 32 + kk) * F_ + q * 4]) = v;
        }
        __syncthreads();
    }
    if (l == 0) {
        v2p[(long long)N_ * F_ + w * 4 + 0] = base0;
        v2p[(long long)N_ * F_ + w * 4 + 1] = base1;
        v2p[(long long)N_ * F_ + w * 4 + 2] = base2;
        v2p[(long long)N_ * F_ + w * 4 + 3] = base3;
    }

    // ---- V1: inclusive suffix of e1*h ----
    base0 = base1 = base2 = base3 = 0.f;
    for (int c = 15; c >= 0; c--) {
        int k = c * 32 + l;
        float ev = se1[k];
        float i0 = ev * tile[k][w * 4 + 0];
        float i1 = ev * tile[k][w * 4 + 1];
        float i2 = ev * tile[k][w * 4 + 2];
        float i3 = ev * tile[k][w * 4 + 3];
        #pragma unroll
        for (int off = 1; off < 32; off <<= 1) {
            float n0 = __shfl_down_sync(0xffffffffu, i0, off);
            float n1 = __shfl_down_sync(0xffffffffu, i1, off);
            float n2 = __shfl_down_sync(0xffffffffu, i2, off);
            float n3 = __shfl_down_sync(0xffffffffu, i3, off);
            if (l + off < 32) { i0 += n0; i1 += n1; i2 += n2; i3 += n3; }
        }
        ob[l][w * 4 + 0] = base0 + i0;
        ob[l][w * 4 + 1] = base1 + i1;
        ob[l][w * 4 + 2] = base2 + i2;
        ob[l][w * 4 + 3] = base3 + i3;
        base0 += __shfl_sync(0xffffffffu, i0, 0);
        base1 += __shfl_sync(0xffffffffu, i1, 0);
        base2 += __shfl_sync(0xffffffffu, i2, 0);
        base3 += __shfl_sync(0xffffffffu, i3, 0);
        __syncthreads();
        {
            int kk = t >> 4, q = t & 15;
            float4 v = make_float4(ob[kk][q*4], ob[kk][q*4+1], ob[kk][q*4+2], ob[kk][q*4+3]);
            *reinterpret_cast<float4*>(&v1p[(long long)(c * 32 + kk) * F_ + q * 4]) = v;
        }
        __syncthreads();
    }
    if (t < 16)
        *reinterpret_cast<float4*>(&v1p[(long long)N_ * F_ + t * 4]) =
            make_float4(0.f, 0.f, 0.f, 0.f);
}

// ============================================================
// Kernel 5c: emit out = c1*V1[t] + c2*V2[t] - ns*h_i.
// ============================================================
__global__ void emit_kernel(const float* __restrict__ h,
                            const float* __restrict__ V1, const float* __restrict__ V2,
                            const int* __restrict__ t_g, const float* __restrict__ c1_g,
                            const float* __restrict__ c2_g, const float* __restrict__ ns_g,
                            float* __restrict__ out, int dorelu) {
    int bh = blockIdx.y;
    int i = blockIdx.x * 4 + (threadIdx.x >> 6);
    int f = threadIdx.x & 63;
    int b = bh >> 2, hd = bh & 3;
    int idx = bh * N_ + i;
    int t = t_g[idx];
    float c1 = c1_g[idx], c2 = c2_g[idx], ns = ns_g[idx];
    long long hoff = ((long long)(b * N_ + i)) * C_ + hd * 64 + f;
    float hv = h[hoff];
    float v1 = V1[((long long)bh * (N_ + 1) + t) * F_ + f];
    float v2 = V2[((long long)bh * (N_ + 1) + t) * F_ + f];
    float o = c1 * v1 + c2 * v2 - ns * hv;
    if (dorelu) o = fmaxf(o, 0.f);
    out[hoff] = o;
}

// ============================================================
// launch
// ============================================================
extern "C" void kernel_launch(void* const* d_in, const int* in_sizes, int n_in,
                              void* d_out, int out_size) {
    int off = (n_in >= 16) ? 1 : 0;
    const int*   player = (const int*)  d_in[0];
    const int*   shot   = (const int*)  d_in[1];
    const float* Ax     = (const float*)d_in[2];
    const float* Ay     = (const float*)d_in[3];
    const float* Bx     = (const float*)d_in[4];
    const float* By     = (const float*)d_in[5];
    const float* emb    = (const float*)d_in[6 + off];
    const float* Wc     = (const float*)d_in[7 + off];
    const float* bc     = (const float*)d_in[8 + off];
    const float* Wm     = (const float*)d_in[9 + off];
    const float* bm     = (const float*)d_in[10 + off];
    const float* lin1   = (const float*)d_in[11 + off];
    const float* att1   = (const float*)d_in[12 + off];
    const float* lin2   = (const float*)d_in[13 + off];
    const float* att2   = (const float*)d_in[14 + off];

    float* out_ne  = (float*)d_out;
    float* out_adj = out_ne + NE_ELEMS;

    float *px, *ph, *po1, *psrc, *pdst;
    float *pe1, *pe2, *pc1, *pc2, *pns, *pV1, *pV2;
    int *psidx, *pt;
    cudaGetSymbolAddress((void**)&px,  g_x);
    cudaGetSymbolAddress((void**)&ph,  g_h);
    cudaGetSymbolAddress((void**)&po1, g_o1);
    cudaGetSymbolAddress((void**)&psrc, g_src);
    cudaGetSymbolAddress((void**)&pdst, g_dst);
    cudaGetSymbolAddress((void**)&psidx, g_sidx);
    cudaGetSymbolAddress((void**)&pe1, g_e1);
    cudaGetSymbolAddress((void**)&pe2, g_e2);
    cudaGetSymbolAddress((void**)&pt,  g_t);
    cudaGetSymbolAddress((void**)&pc1, g_c1);
    cudaGetSymbolAddress((void**)&pc2, g_c2);
    cudaGetSymbolAddress((void**)&pns, g_ns);
    cudaGetSymbolAddress((void**)&pV1, g_V1);
    cudaGetSymbolAddress((void**)&pV2, g_V2);

    if (out_size >= NE_ELEMS + ADJ_ELEMS) {
        fill_kernel<<<dim3(N_ / 16, 14, B_), 256>>>(out_adj);
        scatter_kernel<<<(B_ * S_ + 255) / 256, 256>>>(shot, out_adj);
    }

    feat_kernel<<<B_ * 16, 256>>>(player, Ax, Ay, Bx, By, emb, Wc, bc, Wm, bm, px);

    dim3 ggrid(C_ / 128, (B_ * N_) / 128);
    dim3 egrid(N_ / 4, BH_);
    int sgrid = B_ * N_ * H_ / 8;

    // ---- layer 1 ----
    gemm_kernel<HID><<<ggrid, 256>>>(px, lin1, ph);
    score_kernel<<<sgrid, 256>>>(ph, att1, psrc, pdst);
    sortscan_kernel<<<BH_, N_>>>(psrc, pdst, psidx, pe1, pe2, pt, pc1, pc2, pns);
    vscan_kernel<<<BH_, 512>>>(ph, psidx, pe1, pe2, pV1, pV2);
    emit_kernel<<<egrid, 256>>>(ph, pV1, pV2, pt, pc1, pc2, pns, po1, 1);

    // ---- layer 2 ----
    gemm_kernel<C_><<<ggrid, 256>>>(po1, lin2, ph);
    score_kernel<<<sgrid, 256>>>(ph, att2, psrc, pdst);
    sortscan_kernel<<<BH_, N_>>>(psrc, pdst, psidx, pe1, pe2, pt, pc1, pc2, pns);
    vscan_kernel<<<BH_, 512>>>(ph, psidx, pe1, pe2, pV1, pV2);
    emit_kernel<<<egrid, 256>>>(ph, pV1, pV2, pt, pc1, pc2, pns, out_ne, 0);
}

// round 5
// speedup vs baseline: 1.8410x; 1.1071x over previous
#include <cuda_runtime.h>

// ---------------- problem constants (fixed shapes) ----------------
#define B_    32
#define E_    256
#define N_    512
#define HID   64
#define H_    4
#define F_    64
#define C_    256
#define S_    255
#define BH_   (B_*H_)
#define NE_ELEMS (B_*N_*C_)
#define ADJ_ELEMS (B_*14*N_*N_)
#define MROWS ((B_*N_)/128)          // 128 gemm row-tiles
#define FILL_TOTAL (32*14*32)        // 14336 fill blocks
#define FILL_G64   4096
#define FILL_G256  (FILL_TOTAL - FILL_G64)

// ---------------- scratch ----------------
__device__ float g_x  [B_*N_*HID];
__device__ float g_h  [B_*N_*C_];
__device__ float g_o1 [B_*N_*C_];
__device__ float g_src[BH_*N_];
__device__ float g_dst[BH_*N_];
__device__ int   g_sidx[BH_*N_];
__device__ float g_e1 [BH_*N_];
__device__ float g_e2 [BH_*N_];
__device__ int   g_t  [BH_*N_];
__device__ float g_c1 [BH_*N_];
__device__ float g_c2 [BH_*N_];
__device__ float g_ns [BH_*N_];
__device__ float g_V1 [BH_*(N_+1)*F_];
__device__ float g_V2 [BH_*(N_+1)*F_];

#define FMA4(acc, s, v) { acc.x += (s)*(v).x; acc.y += (s)*(v).y; acc.z += (s)*(v).z; acc.w += (s)*(v).w; }

// ============================================================
// Adjacency fill as a device function (one 256-thread block's share).
// fid in [0, 14336): x = fid&31 (m-tile... actually n-tile), r, b.
// Each thread writes 32 elements of one row.
// ============================================================
__device__ __forceinline__ void fill_block(int fid, int t, float* __restrict__ out) {
    int x = fid & 31;
    int rest = fid >> 5;
    int r = rest % 14;
    int b = rest / 14;
    int n  = x * 16 + (t >> 4);
    int m0 = (t & 15) * 32;
    float* p = out + ((((long long)b * 14 + r) * N_ + n) << 9) + m0;
    float4* p4 = reinterpret_cast<float4*>(p);

    if (r < 13) {
        float4 z = make_float4(0.f, 0.f, 0.f, 0.f);
        #pragma unroll
        for (int q = 0; q < 8; q++) __stcs(p4 + q, z);
        if (r >= 11) {
            int cu = n + 2;
            if (cu < N_ && cu >= m0 && cu < m0 + 32) {
                int rel = ((n & 3) == 0 || (n & 3) == 3) ? 11 : 12;
                if (rel == r) p[cu - m0] = 1.f;
            }
            int cd = n - 2;
            if (cd >= 0 && cd >= m0 && cd < m0 + 32) {
                int pp = n - 2;
                int rel = ((pp & 3) == 0 || (pp & 3) == 3) ? 11 : 12;
                if (rel == r) p[cd - m0] = 1.f;
            }
        }
        return;
    }
    if (n + 3 < m0 || n - 3 >= m0 + 32) {
        float4 o1 = make_float4(1.f, 1.f, 1.f, 1.f);
        #pragma unroll
        for (int q = 0; q < 8; q++) __stcs(p4 + q, o1);
        return;
    }
    int sp1 = -1, sp2 = -1;
    int nm = n & 3;
    if (nm == 0) {
        if (n <= 508) sp1 = n + 3;
        if (n >= 4)   sp2 = n - 1;
    } else if (nm == 3) {
        if (n <= 507) sp1 = n + 1;
        sp2 = n - 3;
    }
    float vals[32];
    #pragma unroll
    for (int q = 0; q < 32; q++) {
        int m = m0 + q;
        bool zero = (m == n) | (m == n - 2) | (m == n + 2) | (m == sp1) | (m == sp2);
        vals[q] = zero ? 0.f : 1.f;
    }
    #pragma unroll
    for (int q = 0; q < 8; q++)
        __stcs(p4 + q, make_float4(vals[4*q], vals[4*q+1], vals[4*q+2], vals[4*q+3]));
}

__global__ void scatter_kernel(const int* __restrict__ shot, float* __restrict__ out) {
    int idx = blockIdx.x * 256 + threadIdx.x;
    if (idx >= B_ * S_) return;
    int b = idx / S_, s = idx % S_;
    int r = shot[idx];
    int i, j;
    if ((s & 1) == 0) { i = 2 * s;     j = 2 * s + 3; }
    else              { i = 2 * s + 1; j = 2 * s + 2; }
    long long base = ((long long)b * 14 + r) * (N_ * N_);
    out[base + (long long)i * N_ + j] = 1.f;
    out[base + (long long)j * N_ + i] = 1.f;
}

// ============================================================
// Kernel 2: node features.
// ============================================================
__global__ void feat_kernel(const int* __restrict__ player,
                            const float* __restrict__ Ax, const float* __restrict__ Ay,
                            const float* __restrict__ Bx, const float* __restrict__ By,
                            const float* __restrict__ emb,
                            const float* __restrict__ Wc, const float* __restrict__ bc,
                            const float* __restrict__ Wm, const float* __restrict__ bm,
                            float* __restrict__ x) {
    __shared__ float feat[32][64];
    __shared__ float wms[64 * 64];
    int blk = blockIdx.x;
    int b = blk >> 4;
    int n0 = (blk & 15) * 32;
    int tid = threadIdx.x;

    #pragma unroll
    for (int it = 0; it < 16; it++) wms[it * 256 + tid] = Wm[it * 256 + tid];

    #pragma unroll
    for (int it = 0; it < 8; it++) {
        int o = it * 256 + tid;
        int nl = o >> 6, c = o & 63;
        int n = n0 + nl;
        int e = n >> 1;
        float val;
        if (c < 32) {
            float cx, cy;
            if ((n & 1) == 0) { cx = Ax[b * E_ + e]; cy = Ay[b * E_ + e]; }
            else              { cx = Bx[b * E_ + e]; cy = By[b * E_ + e]; }
            val = fmaxf(cx * Wc[c] + cy * Wc[32 + c] + bc[c], 0.f);
        } else {
            int pid = player[b * 2 + (n & 1)];
            val = emb[pid * 32 + (c - 32)];
        }
        feat[nl][c] = val;
    }
    __syncthreads();

    #pragma unroll
    for (int it = 0; it < 8; it++) {
        int o = it * 256 + tid;
        int nl = o >> 6, k = o & 63;
        float acc = bm[k];
        #pragma unroll
        for (int c = 0; c < 64; c++) acc += feat[nl][c] * wms[c * 64 + k];
        x[(b * N_ + n0 + nl) * HID + k] = acc;
    }
}

// ============================================================
// Kernel 3: hybrid SGEMM + adjacency fill.
// GEMM: 128x128 tile, 8x8/thread, double-buffered K-chunk 16.
// Blocks with blockIdx.y >= MROWS do adjacency fill instead.
// Thread c-mapping: cols fi*4 and fi*4+64 (conflict-free LDS.128).
// ============================================================
template<int KIN>
__global__ void __launch_bounds__(256, 2)
gemm_fill_kernel(const float* __restrict__ A, const float* __restrict__ W,
                 float* __restrict__ C, float* __restrict__ adj, int fill_base) {
    if (blockIdx.y >= MROWS) {
        int fid = fill_base + (blockIdx.y - MROWS) * 2 + blockIdx.x;
        fill_block(fid, threadIdx.x, adj);
        return;
    }
    __shared__ float As[2][16][132];
    __shared__ float Ws[2][16][128];
    const int Kout = C_;
    int tid = threadIdx.x;
    int mt = blockIdx.y * 128, nt = blockIdx.x * 128;
    int fi = tid & 15, ii = tid >> 4;

    int ar = tid >> 1;              // A row 0..127
    int ak = (tid & 1) * 8;         // k offset 0 or 8
    int wr = tid >> 4;              // W k-row 0..15
    int wc = (tid & 15) * 8;        // W col group

    float4 acc[8][2];
    #pragma unroll
    for (int r = 0; r < 8; r++) {
        acc[r][0] = make_float4(0.f, 0.f, 0.f, 0.f);
        acc[r][1] = make_float4(0.f, 0.f, 0.f, 0.f);
    }

    const float* Arow = &A[(long long)(mt + ar) * KIN];
    // preload chunk 0
    {
        float4 a0 = *reinterpret_cast<const float4*>(&Arow[ak]);
        float4 a1 = *reinterpret_cast<const float4*>(&Arow[ak + 4]);
        As[0][ak + 0][ar] = a0.x; As[0][ak + 1][ar] = a0.y;
        As[0][ak + 2][ar] = a0.z; As[0][ak + 3][ar] = a0.w;
        As[0][ak + 4][ar] = a1.x; As[0][ak + 5][ar] = a1.y;
        As[0][ak + 6][ar] = a1.z; As[0][ak + 7][ar] = a1.w;
        *reinterpret_cast<float4*>(&Ws[0][wr][wc]) =
            *reinterpret_cast<const float4*>(&W[(long long)wr * Kout + nt + wc]);
        *reinterpret_cast<float4*>(&Ws[0][wr][wc + 4]) =
            *reinterpret_cast<const float4*>(&W[(long long)wr * Kout + nt + wc + 4]);
    }
    __syncthreads();

    int buf = 0;
    for (int kt = 0; kt < KIN; kt += 16) {
        bool notlast = (kt + 16 < KIN);
        float4 na0, na1, nw0, nw1;
        if (notlast) {
            na0 = *reinterpret_cast<const float4*>(&Arow[kt + 16 + ak]);
            na1 = *reinterpret_cast<const float4*>(&Arow[kt + 16 + ak + 4]);
            nw0 = *reinterpret_cast<const float4*>(&W[(long long)(kt + 16 + wr) * Kout + nt + wc]);
            nw1 = *reinterpret_cast<const float4*>(&W[(long long)(kt + 16 + wr) * Kout + nt + wc + 4]);
        }
        #pragma unroll
        for (int k = 0; k < 16; k++) {
            float4 av0 = *reinterpret_cast<const float4*>(&As[buf][k][ii * 8]);
            float4 av1 = *reinterpret_cast<const float4*>(&As[buf][k][ii * 8 + 4]);
            float4 bv0 = *reinterpret_cast<const float4*>(&Ws[buf][k][fi * 4]);
            float4 bv1 = *reinterpret_cast<const float4*>(&Ws[buf][k][fi * 4 + 64]);
            FMA4(acc[0][0], av0.x, bv0); FMA4(acc[0][1], av0.x, bv1);
            FMA4(acc[1][0], av0.y, bv0); FMA4(acc[1][1], av0.y, bv1);
            FMA4(acc[2][0], av0.z, bv0); FMA4(acc[2][1], av0.z, bv1);
            FMA4(acc[3][0], av0.w, bv0); FMA4(acc[3][1], av0.w, bv1);
            FMA4(acc[4][0], av1.x, bv0); FMA4(acc[4][1], av1.x, bv1);
            FMA4(acc[5][0], av1.y, bv0); FMA4(acc[5][1], av1.y, bv1);
            FMA4(acc[6][0], av1.z, bv0); FMA4(acc[6][1], av1.z, bv1);
            FMA4(acc[7][0], av1.w, bv0); FMA4(acc[7][1], av1.w, bv1);
        }
        if (notlast) {
            int nb = buf ^ 1;
            As[nb][ak + 0][ar] = na0.x; As[nb][ak + 1][ar] = na0.y;
            As[nb][ak + 2][ar] = na0.z; As[nb][ak + 3][ar] = na0.w;
            As[nb][ak + 4][ar] = na1.x; As[nb][ak + 5][ar] = na1.y;
            As[nb][ak + 6][ar] = na1.z; As[nb][ak + 7][ar] = na1.w;
            *reinterpret_cast<float4*>(&Ws[nb][wr][wc])     = nw0;
            *reinterpret_cast<float4*>(&Ws[nb][wr][wc + 4]) = nw1;
            __syncthreads();
        }
        buf ^= 1;
    }
    #pragma unroll
    for (int r = 0; r < 8; r++) {
        long long base = (long long)(mt + ii * 8 + r) * Kout + nt;
        *reinterpret_cast<float4*>(&C[base + fi * 4])      = acc[r][0];
        *reinterpret_cast<float4*>(&C[base + fi * 4 + 64]) = acc[r][1];
    }
}

// ============================================================
// Kernel 4: scores — one warp per (b,n,head).
// ============================================================
__global__ void score_kernel(const float* __restrict__ h, const float* __restrict__ att,
                             float* __restrict__ ssrc, float* __restrict__ sdst) {
    int gid = blockIdx.x * 8 + (threadIdx.x >> 5);
    int lane = threadIdx.x & 31;
    int bn = gid >> 2, head = gid & 3;
    int b = bn >> 9, n = bn & 511;
    float2 hv = *reinterpret_cast<const float2*>(&h[(long long)bn * C_ + head * 64 + lane * 2]);
    float2 a1 = *reinterpret_cast<const float2*>(&att[head * 128 + lane * 2]);
    float2 a2 = *reinterpret_cast<const float2*>(&att[head * 128 + 64 + lane * 2]);
    float as = hv.x * a1.x + hv.y * a1.y;
    float ad = hv.x * a2.x + hv.y * a2.y;
    #pragma unroll
    for (int off = 16; off >= 1; off >>= 1) {
        as += __shfl_down_sync(0xffffffffu, as, off);
        ad += __shfl_down_sync(0xffffffffu, ad, off);
    }
    if (lane == 0) {
        ssrc[(b * H_ + head) * N_ + n] = as;
        sdst[(b * H_ + head) * N_ + n] = ad;
    }
}

// ============================================================
// Kernel 5a: sort + scalar scans + per-i coeffs.
// ============================================================
__global__ void sortscan_kernel(const float* __restrict__ ssrc, const float* __restrict__ sdst,
                                int* __restrict__ sidx_g, float* __restrict__ e1_g,
                                float* __restrict__ e2_g, int* __restrict__ t_g,
                                float* __restrict__ c1_g, float* __restrict__ c2_g,
                                float* __restrict__ ns_g) {
    int bh = blockIdx.x;
    int i = threadIdx.x;
    __shared__ float sv[N_];
    __shared__ int   si[N_];
    __shared__ float sP1[N_ + 1], sP2[N_ + 1];
    __shared__ float sbuf[N_];

    float bval = sdst[bh * N_ + i];
    sbuf[i] = bval; __syncthreads();
    #pragma unroll
    for (int o = 256; o > 0; o >>= 1) {
        if (i < o) sbuf[i] = fmaxf(sbuf[i], sbuf[i + o]);
        __syncthreads();
    }
    float mb = sbuf[0];
    __syncthreads();

    sv[i] = bval - mb; si[i] = i;
    __syncthreads();
    for (int k = 2; k <= N_; k <<= 1) {
        for (int j = k >> 1; j > 0; j >>= 1) {
            int l = i ^ j;
            if (l > i) {
                bool up = ((i & k) == 0);
                float v0 = sv[i], v1 = sv[l];
                if ((v0 > v1) == up) {
                    sv[i] = v1; sv[l] = v0;
                    int t0 = si[i]; si[i] = si[l]; si[l] = t0;
                }
            }
            __syncthreads();
        }
    }

    float e1 = __expf(sv[i]);
    float e2 = __expf(0.2f * sv[i]);

    sbuf[i] = e2; __syncthreads();
    for (int o = 1; o < N_; o <<= 1) {
        float v = sbuf[i];
        if (i >= o) v += sbuf[i - o];
        __syncthreads();
        sbuf[i] = v;
        __syncthreads();
    }
    sP2[i + 1] = sbuf[i];
    if (i == 0) sP2[0] = 0.f;
    __syncthreads();
    sbuf[i] = e1; __syncthreads();
    for (int o = 1; o < N_; o <<= 1) {
        float v = sbuf[i];
        if (i + o < N_) v += sbuf[i + o];
        __syncthreads();
        sbuf[i] = v;
        __syncthreads();
    }
    sP1[i] = sbuf[i];
    if (i == 0) sP1[N_] = 0.f;
    __syncthreads();

    sidx_g[bh * N_ + i] = si[i];
    e1_g[bh * N_ + i] = e1;
    e2_g[bh * N_ + i] = e2;

    float a = ssrc[bh * N_ + i];
    float thr = -a - mb;
    int lo = 0, hi = N_;
    while (lo < hi) {
        int mid = (lo + hi) >> 1;
        if (sv[mid] > thr) hi = mid; else lo = mid + 1;
    }
    int t = lo;
    float s = a + mb;
    float m = s > 0.f ? s : 0.2f * s;
    float c1v = __expf(s - m);
    float c2v = __expf(0.2f * s - m);
    float sci = a + bval;
    float lsci = sci > 0.f ? sci : 0.2f * sci;
    float ns = __expf(lsci - m);
    float Z = c1v * sP1[t] + c2v * sP2[t] - ns;
    float rz = 1.f / fmaxf(Z, 1e-35f);
    t_g [bh * N_ + i] = t;
    c1_g[bh * N_ + i] = c1v * rz;
    c2_g[bh * N_ + i] = c2v * rz;
    ns_g[bh * N_ + i] = ns * rz;
}

// ============================================================
// Kernel 5b: parallel vector scans.
// ============================================================
__global__ void __launch_bounds__(512, 1)
vscan_kernel(const float* __restrict__ h,
             const int* __restrict__ sidx_g,
             const float* __restrict__ e1_g, const float* __restrict__ e2_g,
             float* __restrict__ V1, float* __restrict__ V2) {
    __shared__ float tile[N_][F_];
    __shared__ float ob[32][65];
    __shared__ float se1[N_], se2[N_];
    int bh = blockIdx.x;
    int b = bh >> 2, hd = bh & 3;
    int t = threadIdx.x;
    const int* sidx = sidx_g + bh * N_;
    const float* hb = h + (long long)b * N_ * C_ + hd * 64;

    se1[t] = e1_g[bh * N_ + t];
    se2[t] = e2_g[bh * N_ + t];
    #pragma unroll
    for (int it = 0; it < 16; it++) {
        int idx = it * 512 + t;
        int k = idx >> 4, q = idx & 15;
        *reinterpret_cast<float4*>(&tile[k][q * 4]) =
            *reinterpret_cast<const float4*>(&hb[(long long)sidx[k] * C_ + q * 4]);
    }
    __syncthreads();

    int w = t >> 5, l = t & 31;
    float* v1p = V1 + (long long)bh * (N_ + 1) * F_;
    float* v2p = V2 + (long long)bh * (N_ + 1) * F_;

    float base0 = 0.f, base1 = 0.f, base2 = 0.f, base3 = 0.f;
    for (int c = 0; c < 16; c++) {
        int k = c * 32 + l;
        float ev = se2[k];
        float v0 = ev * tile[k][w * 4 + 0];
        float v1 = ev * tile[k][w * 4 + 1];
        float v2 = ev * tile[k][w * 4 + 2];
        float v3 = ev * tile[k][w * 4 + 3];
        float i0 = v0, i1 = v1, i2 = v2, i3 = v3;
        #pragma unroll
        for (int off = 1; off < 32; off <<= 1) {
            float n0 = __shfl_up_sync(0xffffffffu, i0, off);
            float n1 = __shfl_up_sync(0xffffffffu, i1, off);
            float n2 = __shfl_up_sync(0xffffffffu, i2, off);
            float n3 = __shfl_up_sync(0xffffffffu, i3, off);
            if (l >= off) { i0 += n0; i1 += n1; i2 += n2; i3 += n3; }
        }
        ob[l][w * 4 + 0] = base0 + i0 - v0;
        ob[l][w * 4 + 1] = base1 + i1 - v1;
        ob[l][w * 4 + 2] = base2 + i2 - v2;
        ob[l][w * 4 + 3] = base3 + i3 - v3;
        base0 += __shfl_sync(0xffffffffu, i0, 31);
        base1 += __shfl_sync(0xffffffffu, i1, 31);
        base2 += __shfl_sync(0xffffffffu, i2, 31);
        base3 += __shfl_sync(0xffffffffu, i3, 31);
        __syncthreads();
        {
            int kk = t >> 4, q = t & 15;
            float4 v = make_float4(ob[kk][q*4], ob[kk][q*4+1], ob[kk][q*4+2], ob[kk][q*4+3]);
            *reinterpret_cast<float4*>(&v2p[(long long)(c * 32 + kk) * F_ + q * 4]) = v;
        }
        __syncthreads();
    }
    if (l == 0) {
        v2p[(long long)N_ * F_ + w * 4 + 0] = base0;
        v2p[(long long)N_ * F_ + w * 4 + 1] = base1;
        v2p[(long long)N_ * F_ + w * 4 + 2] = base2;
        v2p[(long long)N_ * F_ + w * 4 + 3] = base3;
    }

    base0 = base1 = base2 = base3 = 0.f;
    for (int c = 15; c >= 0; c--) {
        int k = c * 32 + l;
        float ev = se1[k];
        float i0 = ev * tile[k][w * 4 + 0];
        float i1 = ev * tile[k][w * 4 + 1];
        float i2 = ev * tile[k][w * 4 + 2];
        float i3 = ev * tile[k][w * 4 + 3];
        #pragma unroll
        for (int off = 1; off < 32; off <<= 1) {
            float n0 = __shfl_down_sync(0xffffffffu, i0, off);
            float n1 = __shfl_down_sync(0xffffffffu, i1, off);
            float n2 = __shfl_down_sync(0xffffffffu, i2, off);
            float n3 = __shfl_down_sync(0xffffffffu, i3, off);
            if (l + off < 32) { i0 += n0; i1 += n1; i2 += n2; i3 += n3; }
        }
        ob[l][w * 4 + 0] = base0 + i0;
        ob[l][w * 4 + 1] = base1 + i1;
        ob[l][w * 4 + 2] = base2 + i2;
        ob[l][w * 4 + 3] = base3 + i3;
        base0 += __shfl_sync(0xffffffffu, i0, 0);
        base1 += __shfl_sync(0xffffffffu, i1, 0);
        base2 += __shfl_sync(0xffffffffu, i2, 0);
        base3 += __shfl_sync(0xffffffffu, i3, 0);
        __syncthreads();
        {
            int kk = t >> 4, q = t & 15;
            float4 v = make_float4(ob[kk][q*4], ob[kk][q*4+1], ob[kk][q*4+2], ob[kk][q*4+3]);
            *reinterpret_cast<float4*>(&v1p[(long long)(c * 32 + kk) * F_ + q * 4]) = v;
        }
        __syncthreads();
    }
    if (t < 16)
        *reinterpret_cast<float4*>(&v1p[(long long)N_ * F_ + t * 4]) =
            make_float4(0.f, 0.f, 0.f, 0.f);
}

// ============================================================
// Kernel 5c: emit.
// ============================================================
__global__ void emit_kernel(const float* __restrict__ h,
                            const float* __restrict__ V1, const float* __restrict__ V2,
                            const int* __restrict__ t_g, const float* __restrict__ c1_g,
                            const float* __restrict__ c2_g, const float* __restrict__ ns_g,
                            float* __restrict__ out, int dorelu) {
    int bh = blockIdx.y;
    int i = blockIdx.x * 4 + (threadIdx.x >> 6);
    int f = threadIdx.x & 63;
    int b = bh >> 2, hd = bh & 3;
    int idx = bh * N_ + i;
    int t = t_g[idx];
    float c1 = c1_g[idx], c2 = c2_g[idx], ns = ns_g[idx];
    long long hoff = ((long long)(b * N_ + i)) * C_ + hd * 64 + f;
    float hv = h[hoff];
    float v1 = V1[((long long)bh * (N_ + 1) + t) * F_ + f];
    float v2 = V2[((long long)bh * (N_ + 1) + t) * F_ + f];
    float o = c1 * v1 + c2 * v2 - ns * hv;
    if (dorelu) o = fmaxf(o, 0.f);
    out[hoff] = o;
}

// ============================================================
// launch
// ============================================================
extern "C" void kernel_launch(void* const* d_in, const int* in_sizes, int n_in,
                              void* d_out, int out_size) {
    int off = (n_in >= 16) ? 1 : 0;
    const int*   player = (const int*)  d_in[0];
    const int*   shot   = (const int*)  d_in[1];
    const float* Ax     = (const float*)d_in[2];
    const float* Ay     = (const float*)d_in[3];
    const float* Bx     = (const float*)d_in[4];
    const float* By     = (const float*)d_in[5];
    const float* emb    = (const float*)d_in[6 + off];
    const float* Wc     = (const float*)d_in[7 + off];
    const float* bc     = (const float*)d_in[8 + off];
    const float* Wm     = (const float*)d_in[9 + off];
    const float* bm     = (const float*)d_in[10 + off];
    const float* lin1   = (const float*)d_in[11 + off];
    const float* att1   = (const float*)d_in[12 + off];
    const float* lin2   = (const float*)d_in[13 + off];
    const float* att2   = (const float*)d_in[14 + off];

    float* out_ne  = (float*)d_out;
    float* out_adj = out_ne + NE_ELEMS;

    float *px, *ph, *po1, *psrc, *pdst;
    float *pe1, *pe2, *pc1, *pc2, *pns, *pV1, *pV2;
    int *psidx, *pt;
    cudaGetSymbolAddress((void**)&px,  g_x);
    cudaGetSymbolAddress((void**)&ph,  g_h);
    cudaGetSymbolAddress((void**)&po1, g_o1);
    cudaGetSymbolAddress((void**)&psrc, g_src);
    cudaGetSymbolAddress((void**)&pdst, g_dst);
    cudaGetSymbolAddress((void**)&psidx, g_sidx);
    cudaGetSymbolAddress((void**)&pe1, g_e1);
    cudaGetSymbolAddress((void**)&pe2, g_e2);
    cudaGetSymbolAddress((void**)&pt,  g_t);
    cudaGetSymbolAddress((void**)&pc1, g_c1);
    cudaGetSymbolAddress((void**)&pc2, g_c2);
    cudaGetSymbolAddress((void**)&pns, g_ns);
    cudaGetSymbolAddress((void**)&pV1, g_V1);
    cudaGetSymbolAddress((void**)&pV2, g_V2);

    int need_adj = (out_size >= NE_ELEMS + ADJ_ELEMS) ? 1 : 0;

    feat_kernel<<<B_ * 16, 256>>>(player, Ax, Ay, Bx, By, emb, Wc, bc, Wm, bm, px);

    dim3 ggrid1(2, MROWS + (need_adj ? FILL_G64  / 2 : 0));
    dim3 ggrid2(2, MROWS + (need_adj ? FILL_G256 / 2 : 0));
    dim3 egrid(N_ / 4, BH_);
    int sgrid = B_ * N_ * H_ / 8;

    // ---- layer 1 (gemm hosts 4096 fill blocks) ----
    gemm_fill_kernel<HID><<<ggrid1, 256>>>(px, lin1, ph, out_adj, 0);
    score_kernel<<<sgrid, 256>>>(ph, att1, psrc, pdst);
    sortscan_kernel<<<BH_, N_>>>(psrc, pdst, psidx, pe1, pe2, pt, pc1, pc2, pns);
    vscan_kernel<<<BH_, 512>>>(ph, psidx, pe1, pe2, pV1, pV2);
    emit_kernel<<<egrid, 256>>>(ph, pV1, pV2, pt, pc1, pc2, pns, po1, 1);

    // ---- layer 2 (gemm hosts 10240 fill blocks) ----
    gemm_fill_kernel<C_><<<ggrid2, 256>>>(po1, lin2, ph, out_adj, FILL_G64);
    score_kernel<<<sgrid, 256>>>(ph, att2, psrc, pdst);
    sortscan_kernel<<<BH_, N_>>>(psrc, pdst, psidx, pe1, pe2, pt, pc1, pc2, pns);
    vscan_kernel<<<BH_, 512>>>(ph, psidx, pe1, pe2, pV1, pV2);
    emit_kernel<<<egrid, 256>>>(ph, pV1, pV2, pt, pc1, pc2, pns, out_ne, 0);

    if (need_adj) scatter_kernel<<<(B_ * S_ + 255) / 256, 256>>>(shot, out_adj);
}

// round 6
// speedup vs baseline: 2.0374x; 1.1067x over previous
#include <cuda_runtime.h>
#include <cstdint>

// ---------------- problem constants ----------------
#define B_    32
#define E_    256
#define N_    512
#define HID   64
#define H_    4
#define F_    64
#define C_    256
#define S_    255
#define BH_   (B_*H_)
#define NE_ELEMS (B_*N_*C_)
#define ADJ_ELEMS (B_*14*N_*N_)
#define MROWS ((B_*N_)/128)          // 128 gemm row-tiles
#define FILL_TOTAL (32*14*32)        // 14336 fill blocks
#define FILL_A (FILL_TOTAL/2)        // 7168
#define FILL_B (FILL_TOTAL - FILL_A)

// smem pitches (bank-conflict-free fragment loads)
#define PA 20
#define PW 136

// ---------------- scratch ----------------
__device__ float g_x  [B_*N_*HID];
__device__ float g_h  [B_*N_*C_];
__device__ float g_o1 [B_*N_*C_];
__device__ int   g_sidx[BH_*N_];
__device__ float g_e1 [BH_*N_];
__device__ float g_e2 [BH_*N_];
__device__ int   g_t  [BH_*N_];
__device__ float g_c1 [BH_*N_];
__device__ float g_c2 [BH_*N_];
__device__ float g_ns [BH_*N_];
__device__ float g_V1 [BH_*(N_+1)*F_];
__device__ float g_V2 [BH_*(N_+1)*F_];

__device__ __forceinline__ float to_tf32(float x) {
    float r; asm("cvt.rna.tf32.f32 %0, %1;" : "=f"(r) : "f"(x)); return r;
}

__device__ __forceinline__ void mma_tf32(float4& d,
                                         uint32_t a0, uint32_t a1, uint32_t a2, uint32_t a3,
                                         uint32_t b0, uint32_t b1) {
    asm("mma.sync.aligned.m16n8k8.row.col.f32.tf32.tf32.f32 "
        "{%0,%1,%2,%3},{%4,%5,%6,%7},{%8,%9},{%0,%1,%2,%3};"
        : "+f"(d.x), "+f"(d.y), "+f"(d.z), "+f"(d.w)
        : "r"(a0), "r"(a1), "r"(a2), "r"(a3), "r"(b0), "r"(b1));
}

// ============================================================
// Adjacency fill device function (one 256-thread block's share).
// ============================================================
__device__ __forceinline__ void fill_block(int fid, int t, float* __restrict__ out) {
    int x = fid & 31;
    int rest = fid >> 5;
    int r = rest % 14;
    int b = rest / 14;
    int n  = x * 16 + (t >> 4);
    int m0 = (t & 15) * 32;
    float* p = out + ((((long long)b * 14 + r) * N_ + n) << 9) + m0;
    float4* p4 = reinterpret_cast<float4*>(p);

    if (r < 13) {
        float4 z = make_float4(0.f, 0.f, 0.f, 0.f);
        #pragma unroll
        for (int q = 0; q < 8; q++) __stcs(p4 + q, z);
        if (r >= 11) {
            int cu = n + 2;
            if (cu < N_ && cu >= m0 && cu < m0 + 32) {
                int rel = ((n & 3) == 0 || (n & 3) == 3) ? 11 : 12;
                if (rel == r) p[cu - m0] = 1.f;
            }
            int cd = n - 2;
            if (cd >= 0 && cd >= m0 && cd < m0 + 32) {
                int pp = n - 2;
                int rel = ((pp & 3) == 0 || (pp & 3) == 3) ? 11 : 12;
                if (rel == r) p[cd - m0] = 1.f;
            }
        }
        return;
    }
    if (n + 3 < m0 || n - 3 >= m0 + 32) {
        float4 o1 = make_float4(1.f, 1.f, 1.f, 1.f);
        #pragma unroll
        for (int q = 0; q < 8; q++) __stcs(p4 + q, o1);
        return;
    }
    int sp1 = -1, sp2 = -1;
    int nm = n & 3;
    if (nm == 0) {
        if (n <= 508) sp1 = n + 3;
        if (n >= 4)   sp2 = n - 1;
    } else if (nm == 3) {
        if (n <= 507) sp1 = n + 1;
        sp2 = n - 3;
    }
    float vals[32];
    #pragma unroll
    for (int q = 0; q < 32; q++) {
        int m = m0 + q;
        bool zero = (m == n) | (m == n - 2) | (m == n + 2) | (m == sp1) | (m == sp2);
        vals[q] = zero ? 0.f : 1.f;
    }
    #pragma unroll
    for (int q = 0; q < 8; q++)
        __stcs(p4 + q, make_float4(vals[4*q], vals[4*q+1], vals[4*q+2], vals[4*q+3]));
}

__global__ void scatter_kernel(const int* __restrict__ shot, float* __restrict__ out) {
    int idx = blockIdx.x * 256 + threadIdx.x;
    if (idx >= B_ * S_) return;
    int b = idx / S_, s = idx % S_;
    int r = shot[idx];
    int i, j;
    if ((s & 1) == 0) { i = 2 * s;     j = 2 * s + 3; }
    else              { i = 2 * s + 1; j = 2 * s + 2; }
    long long base = ((long long)b * 14 + r) * (N_ * N_);
    out[base + (long long)i * N_ + j] = 1.f;
    out[base + (long long)j * N_ + i] = 1.f;
}

// ============================================================
// Kernel 2: node features.
// ============================================================
__global__ void feat_kernel(const int* __restrict__ player,
                            const float* __restrict__ Ax, const float* __restrict__ Ay,
                            const float* __restrict__ Bx, const float* __restrict__ By,
                            const float* __restrict__ emb,
                            const float* __restrict__ Wc, const float* __restrict__ bc,
                            const float* __restrict__ Wm, const float* __restrict__ bm,
                            float* __restrict__ x) {
    __shared__ float feat[32][64];
    __shared__ float wms[64 * 64];
    int blk = blockIdx.x;
    int b = blk >> 4;
    int n0 = (blk & 15) * 32;
    int tid = threadIdx.x;

    #pragma unroll
    for (int it = 0; it < 16; it++) wms[it * 256 + tid] = Wm[it * 256 + tid];

    #pragma unroll
    for (int it = 0; it < 8; it++) {
        int o = it * 256 + tid;
        int nl = o >> 6, c = o & 63;
        int n = n0 + nl;
        int e = n >> 1;
        float val;
        if (c < 32) {
            float cx, cy;
            if ((n & 1) == 0) { cx = Ax[b * E_ + e]; cy = Ay[b * E_ + e]; }
            else              { cx = Bx[b * E_ + e]; cy = By[b * E_ + e]; }
            val = fmaxf(cx * Wc[c] + cy * Wc[32 + c] + bc[c], 0.f);
        } else {
            int pid = player[b * 2 + (n & 1)];
            val = emb[pid * 32 + (c - 32)];
        }
        feat[nl][c] = val;
    }
    __syncthreads();

    #pragma unroll
    for (int it = 0; it < 8; it++) {
        int o = it * 256 + tid;
        int nl = o >> 6, k = o & 63;
        float acc = bm[k];
        #pragma unroll
        for (int c = 0; c < 64; c++) acc += feat[nl][c] * wms[c * 64 + k];
        x[(b * N_ + n0 + nl) * HID + k] = acc;
    }
}

// ============================================================
// Kernel 3: hybrid tf32-MMA SGEMM + adjacency fill.
// GEMM: 128x128 block tile, 8 warps as 4(M)x2(N); warp tile 32x64;
// mma.sync m16n8k8 tf32, double-buffered K-chunk 16.
// Blocks with blockIdx.y >= MROWS do adjacency fill instead.
// ============================================================
template<int KIN>
__global__ void __launch_bounds__(256, 2)
gemm_fill_kernel(const float* __restrict__ A, const float* __restrict__ W,
                 float* __restrict__ C, float* __restrict__ adj, int fill_base) {
    if (blockIdx.y >= MROWS) {
        int fid = fill_base + (blockIdx.y - MROWS) * 2 + blockIdx.x;
        fill_block(fid, threadIdx.x, adj);
        return;
    }
    __shared__ float As[2][128 * PA];
    __shared__ float Ws[2][16 * PW];
    const int Kout = C_;
    int tid = threadIdx.x;
    int mt = blockIdx.y * 128, nt = blockIdx.x * 128;
    int wid = tid >> 5, lane = tid & 31;
    int g = lane >> 2, t4 = lane & 3;
    int m0w = (wid >> 1) * 32;        // warp M offset (4 warps in M)
    int n0w = (wid & 1) * 64;         // warp N offset (2 warps in N)

    int ar = tid >> 1;                // A staging: row 0..127
    int ak = (tid & 1) * 8;           // k offset 0/8
    int wr = tid >> 4;                // W staging: k row 0..15
    int wc = (tid & 15) * 8;          // col group

    float4 acc[2][8];
    #pragma unroll
    for (int mi = 0; mi < 2; mi++)
        #pragma unroll
        for (int ni = 0; ni < 8; ni++) acc[mi][ni] = make_float4(0.f, 0.f, 0.f, 0.f);

    const float* Arow = &A[(long long)(mt + ar) * KIN];

    // preload chunk 0
    {
        float4 a0 = *reinterpret_cast<const float4*>(&Arow[ak]);
        float4 a1 = *reinterpret_cast<const float4*>(&Arow[ak + 4]);
        float* d = &As[0][ar * PA + ak];
        d[0] = to_tf32(a0.x); d[1] = to_tf32(a0.y); d[2] = to_tf32(a0.z); d[3] = to_tf32(a0.w);
        d[4] = to_tf32(a1.x); d[5] = to_tf32(a1.y); d[6] = to_tf32(a1.z); d[7] = to_tf32(a1.w);
        float4 w0 = *reinterpret_cast<const float4*>(&W[(long long)wr * Kout + nt + wc]);
        float4 w1 = *reinterpret_cast<const float4*>(&W[(long long)wr * Kout + nt + wc + 4]);
        float* e = &Ws[0][wr * PW + wc];
        e[0] = to_tf32(w0.x); e[1] = to_tf32(w0.y); e[2] = to_tf32(w0.z); e[3] = to_tf32(w0.w);
        e[4] = to_tf32(w1.x); e[5] = to_tf32(w1.y); e[6] = to_tf32(w1.z); e[7] = to_tf32(w1.w);
    }
    __syncthreads();

    int buf = 0;
    for (int kt = 0; kt < KIN; kt += 16) {
        bool notlast = (kt + 16 < KIN);
        float4 na0, na1, nw0, nw1;
        if (notlast) {
            na0 = *reinterpret_cast<const float4*>(&Arow[kt + 16 + ak]);
            na1 = *reinterpret_cast<const float4*>(&Arow[kt + 16 + ak + 4]);
            nw0 = *reinterpret_cast<const float4*>(&W[(long long)(kt + 16 + wr) * Kout + nt + wc]);
            nw1 = *reinterpret_cast<const float4*>(&W[(long long)(kt + 16 + wr) * Kout + nt + wc + 4]);
        }
        const float* Ab = As[buf];
        const float* Wb = Ws[buf];
        #pragma unroll
        for (int ks = 0; ks < 16; ks += 8) {
            uint32_t af[2][4];
            #pragma unroll
            for (int mi = 0; mi < 2; mi++) {
                int r0 = m0w + mi * 16 + g;
                af[mi][0] = __float_as_uint(Ab[(r0    ) * PA + ks + t4    ]);
                af[mi][1] = __float_as_uint(Ab[(r0 + 8) * PA + ks + t4    ]);
                af[mi][2] = __float_as_uint(Ab[(r0    ) * PA + ks + t4 + 4]);
                af[mi][3] = __float_as_uint(Ab[(r0 + 8) * PA + ks + t4 + 4]);
            }
            uint32_t bf[8][2];
            #pragma unroll
            for (int ni = 0; ni < 8; ni++) {
                int c0 = n0w + ni * 8 + g;
                bf[ni][0] = __float_as_uint(Wb[(ks + t4    ) * PW + c0]);
                bf[ni][1] = __float_as_uint(Wb[(ks + t4 + 4) * PW + c0]);
            }
            #pragma unroll
            for (int mi = 0; mi < 2; mi++)
                #pragma unroll
                for (int ni = 0; ni < 8; ni++)
                    mma_tf32(acc[mi][ni], af[mi][0], af[mi][1], af[mi][2], af[mi][3],
                             bf[ni][0], bf[ni][1]);
        }
        if (notlast) {
            int nb = buf ^ 1;
            float* d = &As[nb][ar * PA + ak];
            d[0] = to_tf32(na0.x); d[1] = to_tf32(na0.y); d[2] = to_tf32(na0.z); d[3] = to_tf32(na0.w);
            d[4] = to_tf32(na1.x); d[5] = to_tf32(na1.y); d[6] = to_tf32(na1.z); d[7] = to_tf32(na1.w);
            float* e = &Ws[nb][wr * PW + wc];
            e[0] = to_tf32(nw0.x); e[1] = to_tf32(nw0.y); e[2] = to_tf32(nw0.z); e[3] = to_tf32(nw0.w);
            e[4] = to_tf32(nw1.x); e[5] = to_tf32(nw1.y); e[6] = to_tf32(nw1.z); e[7] = to_tf32(nw1.w);
            __syncthreads();
        }
        buf ^= 1;
    }

    // epilogue: d layout c0(row g,col 2t), c1(+1), c2(row g+8), c3(+1)
    #pragma unroll
    for (int mi = 0; mi < 2; mi++) {
        #pragma unroll
        for (int ni = 0; ni < 8; ni++) {
            int row = mt + m0w + mi * 16 + g;
            int col = nt + n0w + ni * 8 + 2 * t4;
            float4 v = acc[mi][ni];
            *reinterpret_cast<float2*>(&C[(long long)row * Kout + col]) = make_float2(v.x, v.y);
            *reinterpret_cast<float2*>(&C[(long long)(row + 8) * Kout + col]) = make_float2(v.z, v.w);
        }
    }
}

// ============================================================
// Kernel 5a: fused score + sort + scalar scans + per-i coeffs.
// Block = (b,h), 512 threads; thread i computes a_i, b_i itself.
// ============================================================
__global__ void sortscan_kernel(const float* __restrict__ h, const float* __restrict__ att,
                                int* __restrict__ sidx_g, float* __restrict__ e1_g,
                                float* __restrict__ e2_g, int* __restrict__ t_g,
                                float* __restrict__ c1_g, float* __restrict__ c2_g,
                                float* __restrict__ ns_g) {
    int bh = blockIdx.x;
    int b = bh >> 2, hd = bh & 3;
    int i = threadIdx.x;
    __shared__ float satt[128];
    __shared__ float sv[N_];
    __shared__ int   si[N_];
    __shared__ float sP1[N_ + 1], sP2[N_ + 1];
    __shared__ float sbuf[N_];

    if (i < 128) satt[i] = att[hd * 128 + i];
    __syncthreads();

    // per-node scores
    const float4* hrow = reinterpret_cast<const float4*>(&h[((long long)(b * N_ + i)) * C_ + hd * 64]);
    float a = 0.f, bval = 0.f;
    #pragma unroll
    for (int q = 0; q < 16; q++) {
        float4 v = hrow[q];
        float4 w1 = *reinterpret_cast<const float4*>(&satt[q * 4]);
        float4 w2 = *reinterpret_cast<const float4*>(&satt[64 + q * 4]);
        a    += v.x * w1.x + v.y * w1.y + v.z * w1.z + v.w * w1.w;
        bval += v.x * w2.x + v.y * w2.y + v.z * w2.z + v.w * w2.w;
    }

    sbuf[i] = bval; __syncthreads();
    #pragma unroll
    for (int o = 256; o > 0; o >>= 1) {
        if (i < o) sbuf[i] = fmaxf(sbuf[i], sbuf[i + o]);
        __syncthreads();
    }
    float mb = sbuf[0];
    __syncthreads();

    sv[i] = bval - mb; si[i] = i;
    __syncthreads();
    for (int k = 2; k <= N_; k <<= 1) {
        for (int j = k >> 1; j > 0; j >>= 1) {
            int l = i ^ j;
            if (l > i) {
                bool up = ((i & k) == 0);
                float v0 = sv[i], v1 = sv[l];
                if ((v0 > v1) == up) {
                    sv[i] = v1; sv[l] = v0;
                    int t0 = si[i]; si[i] = si[l]; si[l] = t0;
                }
            }
            __syncthreads();
        }
    }

    float e1 = __expf(sv[i]);
    float e2 = __expf(0.2f * sv[i]);

    sbuf[i] = e2; __syncthreads();
    for (int o = 1; o < N_; o <<= 1) {
        float v = sbuf[i];
        if (i >= o) v += sbuf[i - o];
        __syncthreads();
        sbuf[i] = v;
        __syncthreads();
    }
    sP2[i + 1] = sbuf[i];
    if (i == 0) sP2[0] = 0.f;
    __syncthreads();
    sbuf[i] = e1; __syncthreads();
    for (int o = 1; o < N_; o <<= 1) {
        float v = sbuf[i];
        if (i + o < N_) v += sbuf[i + o];
        __syncthreads();
        sbuf[i] = v;
        __syncthreads();
    }
    sP1[i] = sbuf[i];
    if (i == 0) sP1[N_] = 0.f;
    __syncthreads();

    sidx_g[bh * N_ + i] = si[i];
    e1_g[bh * N_ + i] = e1;
    e2_g[bh * N_ + i] = e2;

    float thr = -a - mb;
    int lo = 0, hi = N_;
    while (lo < hi) {
        int mid = (lo + hi) >> 1;
        if (sv[mid] > thr) hi = mid; else lo = mid + 1;
    }
    int t = lo;
    float s = a + mb;
    float m = s > 0.f ? s : 0.2f * s;
    float c1v = __expf(s - m);
    float c2v = __expf(0.2f * s - m);
    float sci = a + bval;
    float lsci = sci > 0.f ? sci : 0.2f * sci;
    float ns = __expf(lsci - m);
    float Z = c1v * sP1[t] + c2v * sP2[t] - ns;
    float rz = 1.f / fmaxf(Z, 1e-35f);
    t_g [bh * N_ + i] = t;
    c1_g[bh * N_ + i] = c1v * rz;
    c2_g[bh * N_ + i] = c2v * rz;
    ns_g[bh * N_ + i] = ns * rz;
}

// ============================================================
// Kernel 5b: parallel vector scans.
// ============================================================
__global__ void __launch_bounds__(512, 1)
vscan_kernel(const float* __restrict__ h,
             const int* __restrict__ sidx_g,
             const float* __restrict__ e1_g, const float* __restrict__ e2_g,
             float* __restrict__ V1, float* __restrict__ V2) {
    __shared__ float tile[N_][F_];
    __shared__ float ob[32][65];
    __shared__ float se1[N_], se2[N_];
    int bh = blockIdx.x;
    int b = bh >> 2, hd = bh & 3;
    int t = threadIdx.x;
    const int* sidx = sidx_g + bh * N_;
    const float* hb = h + (long long)b * N_ * C_ + hd * 64;

    se1[t] = e1_g[bh * N_ + t];
    se2[t] = e2_g[bh * N_ + t];
    #pragma unroll
    for (int it = 0; it < 16; it++) {
        int idx = it * 512 + t;
        int k = idx >> 4, q = idx & 15;
        *reinterpret_cast<float4*>(&tile[k][q * 4]) =
            *reinterpret_cast<const float4*>(&hb[(long long)sidx[k] * C_ + q * 4]);
    }
    __syncthreads();

    int w = t >> 5, l = t & 31;
    float* v1p = V1 + (long long)bh * (N_ + 1) * F_;
    float* v2p = V2 + (long long)bh * (N_ + 1) * F_;

    float base0 = 0.f, base1 = 0.f, base2 = 0.f, base3 = 0.f;
    for (int c = 0; c < 16; c++) {
        int k = c * 32 + l;
        float ev = se2[k];
        float v0 = ev * tile[k][w * 4 + 0];
        float v1 = ev * tile[k][w * 4 + 1];
        float v2 = ev * tile[k][w * 4 + 2];
        float v3 = ev * tile[k][w * 4 + 3];
        float i0 = v0, i1 = v1, i2 = v2, i3 = v3;
        #pragma unroll
        for (int off = 1; off < 32; off <<= 1) {
            float n0 = __shfl_up_sync(0xffffffffu, i0, off);
            float n1 = __shfl_up_sync(0xffffffffu, i1, off);
            float n2 = __shfl_up_sync(0xffffffffu, i2, off);
            float n3 = __shfl_up_sync(0xffffffffu, i3, off);
            if (l >= off) { i0 += n0; i1 += n1; i2 += n2; i3 += n3; }
        }
        ob[l][w * 4 + 0] = base0 + i0 - v0;
        ob[l][w * 4 + 1] = base1 + i1 - v1;
        ob[l][w * 4 + 2] = base2 + i2 - v2;
        ob[l][w * 4 + 3] = base3 + i3 - v3;
        base0 += __shfl_sync(0xffffffffu, i0, 31);
        base1 += __shfl_sync(0xffffffffu, i1, 31);
        base2 += __shfl_sync(0xffffffffu, i2, 31);
        base3 += __shfl_sync(0xffffffffu, i3, 31);
        __syncthreads();
        {
            int kk = t >> 4, q = t & 15;
            float4 v = make_float4(ob[kk][q*4], ob[kk][q*4+1], ob[kk][q*4+2], ob[kk][q*4+3]);
            *reinterpret_cast<float4*>(&v2p[(long long)(c * 32 + kk) * F_ + q * 4]) = v;
        }
        __syncthreads();
    }
    if (l == 0) {
        v2p[(long long)N_ * F_ + w * 4 + 0] = base0;
        v2p[(long long)N_ * F_ + w * 4 + 1] = base1;
        v2p[(long long)N_ * F_ + w * 4 + 2] = base2;
        v2p[(long long)N_ * F_ + w * 4 + 3] = base3;
    }

    base0 = base1 = base2 = base3 = 0.f;
    for (int c = 15; c >= 0; c--) {
        int k = c * 32 + l;
        float ev = se1[k];
        float i0 = ev * tile[k][w * 4 + 0];
        float i1 = ev * tile[k][w * 4 + 1];
        float i2 = ev * tile[k][w * 4 + 2];
        float i3 = ev * tile[k][w * 4 + 3];
        #pragma unroll
        for (int off = 1; off < 32; off <<= 1) {
            float n0 = __shfl_down_sync(0xffffffffu, i0, off);
            float n1 = __shfl_down_sync(0xffffffffu, i1, off);
            float n2 = __shfl_down_sync(0xffffffffu, i2, off);
            float n3 = __shfl_down_sync(0xffffffffu, i3, off);
            if (l + off < 32) { i0 += n0; i1 += n1; i2 += n2; i3 += n3; }
        }
        ob[l][w * 4 + 0] = base0 + i0;
        ob[l][w * 4 + 1] = base1 + i1;
        ob[l][w * 4 + 2] = base2 + i2;
        ob[l][w * 4 + 3] = base3 + i3;
        base0 += __shfl_sync(0xffffffffu, i0, 0);
        base1 += __shfl_sync(0xffffffffu, i1, 0);
        base2 += __shfl_sync(0xffffffffu, i2, 0);
        base3 += __shfl_sync(0xffffffffu, i3, 0);
        __syncthreads();
        {
            int kk = t >> 4, q = t & 15;
            float4 v = make_float4(ob[kk][q*4], ob[kk][q*4+1], ob[kk][q*4+2], ob[kk][q*4+3]);
            *reinterpret_cast<float4*>(&v1p[(long long)(c * 32 + kk) * F_ + q * 4]) = v;
        }
        __syncthreads();
    }
    if (t < 16)
        *reinterpret_cast<float4*>(&v1p[(long long)N_ * F_ + t * 4]) =
            make_float4(0.f, 0.f, 0.f, 0.f);
}

// ============================================================
// Kernel 5c: emit.
// ============================================================
__global__ void emit_kernel(const float* __restrict__ h,
                            const float* __restrict__ V1, const float* __restrict__ V2,
                            const int* __restrict__ t_g, const float* __restrict__ c1_g,
                            const float* __restrict__ c2_g, const float* __restrict__ ns_g,
                            float* __restrict__ out, int dorelu) {
    int bh = blockIdx.y;
    int i = blockIdx.x * 4 + (threadIdx.x >> 6);
    int f = threadIdx.x & 63;
    int b = bh >> 2, hd = bh & 3;
    int idx = bh * N_ + i;
    int t = t_g[idx];
    float c1 = c1_g[idx], c2 = c2_g[idx], ns = ns_g[idx];
    long long hoff = ((long long)(b * N_ + i)) * C_ + hd * 64 + f;
    float hv = h[hoff];
    float v1 = V1[((long long)bh * (N_ + 1) + t) * F_ + f];
    float v2 = V2[((long long)bh * (N_ + 1) + t) * F_ + f];
    float o = c1 * v1 + c2 * v2 - ns * hv;
    if (dorelu) o = fmaxf(o, 0.f);
    out[hoff] = o;
}

// ============================================================
// launch
// ============================================================
extern "C" void kernel_launch(void* const* d_in, const int* in_sizes, int n_in,
                              void* d_out, int out_size) {
    int off = (n_in >= 16) ? 1 : 0;
    const int*   player = (const int*)  d_in[0];
    const int*   shot   = (const int*)  d_in[1];
    const float* Ax     = (const float*)d_in[2];
    const float* Ay     = (const float*)d_in[3];
    const float* Bx     = (const float*)d_in[4];
    const float* By     = (const float*)d_in[5];
    const float* emb    = (const float*)d_in[6 + off];
    const float* Wc     = (const float*)d_in[7 + off];
    const float* bc     = (const float*)d_in[8 + off];
    const float* Wm     = (const float*)d_in[9 + off];
    const float* bm     = (const float*)d_in[10 + off];
    const float* lin1   = (const float*)d_in[11 + off];
    const float* att1   = (const float*)d_in[12 + off];
    const float* lin2   = (const float*)d_in[13 + off];
    const float* att2   = (const float*)d_in[14 + off];

    float* out_ne  = (float*)d_out;
    float* out_adj = out_ne + NE_ELEMS;

    float *px, *ph, *po1;
    float *pe1, *pe2, *pc1, *pc2, *pns, *pV1, *pV2;
    int *psidx, *pt;
    cudaGetSymbolAddress((void**)&px,  g_x);
    cudaGetSymbolAddress((void**)&ph,  g_h);
    cudaGetSymbolAddress((void**)&po1, g_o1);
    cudaGetSymbolAddress((void**)&psidx, g_sidx);
    cudaGetSymbolAddress((void**)&pe1, g_e1);
    cudaGetSymbolAddress((void**)&pe2, g_e2);
    cudaGetSymbolAddress((void**)&pt,  g_t);
    cudaGetSymbolAddress((void**)&pc1, g_c1);
    cudaGetSymbolAddress((void**)&pc2, g_c2);
    cudaGetSymbolAddress((void**)&pns, g_ns);
    cudaGetSymbolAddress((void**)&pV1, g_V1);
    cudaGetSymbolAddress((void**)&pV2, g_V2);

    int need_adj = (out_size >= NE_ELEMS + ADJ_ELEMS) ? 1 : 0;

    feat_kernel<<<B_ * 16, 256>>>(player, Ax, Ay, Bx, By, emb, Wc, bc, Wm, bm, px);

    dim3 ggrid1(2, MROWS + (need_adj ? FILL_A / 2 : 0));
    dim3 ggrid2(2, MROWS + (need_adj ? FILL_B / 2 : 0));
    dim3 egrid(N_ / 4, BH_);

    // ---- layer 1 ----
    gemm_fill_kernel<HID><<<ggrid1, 256>>>(px, lin1, ph, out_adj, 0);
    sortscan_kernel<<<BH_, N_>>>(ph, att1, psidx, pe1, pe2, pt, pc1, pc2, pns);
    vscan_kernel<<<BH_, 512>>>(ph, psidx, pe1, pe2, pV1, pV2);
    emit_kernel<<<egrid, 256>>>(ph, pV1, pV2, pt, pc1, pc2, pns, po1, 1);

    // ---- layer 2 ----
    gemm_fill_kernel<C_><<<ggrid2, 256>>>(po1, lin2, ph, out_adj, FILL_A);
    sortscan_kernel<<<BH_, N_>>>(ph, att2, psidx, pe1, pe2, pt, pc1, pc2, pns);
    vscan_kernel<<<BH_, 512>>>(ph, psidx, pe1, pe2, pV1, pV2);
    emit_kernel<<<egrid, 256>>>(ph, pV1, pV2, pt, pc1, pc2, pns, out_ne, 0);

    if (need_adj) scatter_kernel<<<(B_ * S_ + 255) / 256, 256>>>(shot, out_adj);
}

// round 7
// speedup vs baseline: 2.4246x; 1.1900x over previous
#include <cuda_runtime.h>
#include <cstdint>

// ---------------- problem constants ----------------
#define B_    32
#define E_    256
#define N_    512
#define HID   64
#define H_    4
#define F_    64
#define C_    256
#define S_    255
#define BH_   (B_*H_)
#define NE_ELEMS (B_*N_*C_)
#define ADJ_ELEMS (B_*14*N_*N_)
#define MROWS ((B_*N_)/128)
#define FILL_TOTAL (32*14*32)
#define FILL_A (FILL_TOTAL/2)
#define FILL_B (FILL_TOTAL - FILL_A)

#define PA 20
#define PW 136

// ---------------- scratch ----------------
__device__ float g_x  [B_*N_*HID];
__device__ float g_h  [B_*N_*C_];
__device__ float g_o1 [B_*N_*C_];
__device__ int   g_sidx[BH_*N_];
__device__ float g_e1 [BH_*N_];
__device__ float g_e2 [BH_*N_];
__device__ int   g_t  [BH_*N_];
__device__ float g_c1 [BH_*N_];
__device__ float g_c2 [BH_*N_];
__device__ float g_ns [BH_*N_];

__device__ __forceinline__ float to_tf32(float x) {
    float r; asm("cvt.rna.tf32.f32 %0, %1;" : "=f"(r) : "f"(x)); return r;
}

__device__ __forceinline__ void mma_tf32(float4& d,
                                         uint32_t a0, uint32_t a1, uint32_t a2, uint32_t a3,
                                         uint32_t b0, uint32_t b1) {
    asm("mma.sync.aligned.m16n8k8.row.col.f32.tf32.tf32.f32 "
        "{%0,%1,%2,%3},{%4,%5,%6,%7},{%8,%9},{%0,%1,%2,%3};"
        : "+f"(d.x), "+f"(d.y), "+f"(d.z), "+f"(d.w)
        : "r"(a0), "r"(a1), "r"(a2), "r"(a3), "r"(b0), "r"(b1));
}

// ============================================================
// Adjacency fill (one 256-thread block's share).
// ============================================================
__device__ __forceinline__ void fill_block(int fid, int t, float* __restrict__ out) {
    int x = fid & 31;
    int rest = fid >> 5;
    int r = rest % 14;
    int b = rest / 14;
    int n  = x * 16 + (t >> 4);
    int m0 = (t & 15) * 32;
    float* p = out + ((((long long)b * 14 + r) * N_ + n) << 9) + m0;
    float4* p4 = reinterpret_cast<float4*>(p);

    if (r < 13) {
        float4 z = make_float4(0.f, 0.f, 0.f, 0.f);
        #pragma unroll
        for (int q = 0; q < 8; q++) __stcs(p4 + q, z);
        if (r >= 11) {
            int cu = n + 2;
            if (cu < N_ && cu >= m0 && cu < m0 + 32) {
                int rel = ((n & 3) == 0 || (n & 3) == 3) ? 11 : 12;
                if (rel == r) p[cu - m0] = 1.f;
            }
            int cd = n - 2;
            if (cd >= 0 && cd >= m0 && cd < m0 + 32) {
                int pp = n - 2;
                int rel = ((pp & 3) == 0 || (pp & 3) == 3) ? 11 : 12;
                if (rel == r) p[cd - m0] = 1.f;
            }
        }
        return;
    }
    if (n + 3 < m0 || n - 3 >= m0 + 32) {
        float4 o1 = make_float4(1.f, 1.f, 1.f, 1.f);
        #pragma unroll
        for (int q = 0; q < 8; q++) __stcs(p4 + q, o1);
        return;
    }
    int sp1 = -1, sp2 = -1;
    int nm = n & 3;
    if (nm == 0) {
        if (n <= 508) sp1 = n + 3;
        if (n >= 4)   sp2 = n - 1;
    } else if (nm == 3) {
        if (n <= 507) sp1 = n + 1;
        sp2 = n - 3;
    }
    float vals[32];
    #pragma unroll
    for (int q = 0; q < 32; q++) {
        int m = m0 + q;
        bool zero = (m == n) | (m == n - 2) | (m == n + 2) | (m == sp1) | (m == sp2);
        vals[q] = zero ? 0.f : 1.f;
    }
    #pragma unroll
    for (int q = 0; q < 8; q++)
        __stcs(p4 + q, make_float4(vals[4*q], vals[4*q+1], vals[4*q+2], vals[4*q+3]));
}

__global__ void scatter_kernel(const int* __restrict__ shot, float* __restrict__ out) {
    int idx = blockIdx.x * 256 + threadIdx.x;
    if (idx >= B_ * S_) return;
    int b = idx / S_, s = idx % S_;
    int r = shot[idx];
    int i, j;
    if ((s & 1) == 0) { i = 2 * s;     j = 2 * s + 3; }
    else              { i = 2 * s + 1; j = 2 * s + 2; }
    long long base = ((long long)b * 14 + r) * (N_ * N_);
    out[base + (long long)i * N_ + j] = 1.f;
    out[base + (long long)j * N_ + i] = 1.f;
}

// ============================================================
// Kernel 2: node features.
// ============================================================
__global__ void feat_kernel(const int* __restrict__ player,
                            const float* __restrict__ Ax, const float* __restrict__ Ay,
                            const float* __restrict__ Bx, const float* __restrict__ By,
                            const float* __restrict__ emb,
                            const float* __restrict__ Wc, const float* __restrict__ bc,
                            const float* __restrict__ Wm, const float* __restrict__ bm,
                            float* __restrict__ x) {
    __shared__ float feat[32][64];
    __shared__ float wms[64 * 64];
    int blk = blockIdx.x;
    int b = blk >> 4;
    int n0 = (blk & 15) * 32;
    int tid = threadIdx.x;

    #pragma unroll
    for (int it = 0; it < 16; it++) wms[it * 256 + tid] = Wm[it * 256 + tid];

    #pragma unroll
    for (int it = 0; it < 8; it++) {
        int o = it * 256 + tid;
        int nl = o >> 6, c = o & 63;
        int n = n0 + nl;
        int e = n >> 1;
        float val;
        if (c < 32) {
            float cx, cy;
            if ((n & 1) == 0) { cx = Ax[b * E_ + e]; cy = Ay[b * E_ + e]; }
            else              { cx = Bx[b * E_ + e]; cy = By[b * E_ + e]; }
            val = fmaxf(cx * Wc[c] + cy * Wc[32 + c] + bc[c], 0.f);
        } else {
            int pid = player[b * 2 + (n & 1)];
            val = emb[pid * 32 + (c - 32)];
        }
        feat[nl][c] = val;
    }
    __syncthreads();

    #pragma unroll
    for (int it = 0; it < 8; it++) {
        int o = it * 256 + tid;
        int nl = o >> 6, k = o & 63;
        float acc = bm[k];
        #pragma unroll
        for (int c = 0; c < 64; c++) acc += feat[nl][c] * wms[c * 64 + k];
        x[(b * N_ + n0 + nl) * HID + k] = acc;
    }
}

// ============================================================
// Kernel 3: hybrid tf32-MMA SGEMM + adjacency fill.
// ============================================================
template<int KIN>
__global__ void __launch_bounds__(256, 2)
gemm_fill_kernel(const float* __restrict__ A, const float* __restrict__ W,
                 float* __restrict__ C, float* __restrict__ adj, int fill_base) {
    if (blockIdx.y >= MROWS) {
        int fid = fill_base + (blockIdx.y - MROWS) * 2 + blockIdx.x;
        fill_block(fid, threadIdx.x, adj);
        return;
    }
    __shared__ float As[2][128 * PA];
    __shared__ float Ws[2][16 * PW];
    const int Kout = C_;
    int tid = threadIdx.x;
    int mt = blockIdx.y * 128, nt = blockIdx.x * 128;
    int wid = tid >> 5, lane = tid & 31;
    int g = lane >> 2, t4 = lane & 3;
    int m0w = (wid >> 1) * 32;
    int n0w = (wid & 1) * 64;

    int ar = tid >> 1;
    int ak = (tid & 1) * 8;
    int wr = tid >> 4;
    int wc = (tid & 15) * 8;

    float4 acc[2][8];
    #pragma unroll
    for (int mi = 0; mi < 2; mi++)
        #pragma unroll
        for (int ni = 0; ni < 8; ni++) acc[mi][ni] = make_float4(0.f, 0.f, 0.f, 0.f);

    const float* Arow = &A[(long long)(mt + ar) * KIN];

    {
        float4 a0 = *reinterpret_cast<const float4*>(&Arow[ak]);
        float4 a1 = *reinterpret_cast<const float4*>(&Arow[ak + 4]);
        float* d = &As[0][ar * PA + ak];
        d[0] = to_tf32(a0.x); d[1] = to_tf32(a0.y); d[2] = to_tf32(a0.z); d[3] = to_tf32(a0.w);
        d[4] = to_tf32(a1.x); d[5] = to_tf32(a1.y); d[6] = to_tf32(a1.z); d[7] = to_tf32(a1.w);
        float4 w0 = *reinterpret_cast<const float4*>(&W[(long long)wr * Kout + nt + wc]);
        float4 w1 = *reinterpret_cast<const float4*>(&W[(long long)wr * Kout + nt + wc + 4]);
        float* e = &Ws[0][wr * PW + wc];
        e[0] = to_tf32(w0.x); e[1] = to_tf32(w0.y); e[2] = to_tf32(w0.z); e[3] = to_tf32(w0.w);
        e[4] = to_tf32(w1.x); e[5] = to_tf32(w1.y); e[6] = to_tf32(w1.z); e[7] = to_tf32(w1.w);
    }
    __syncthreads();

    int buf = 0;
    for (int kt = 0; kt < KIN; kt += 16) {
        bool notlast = (kt + 16 < KIN);
        float4 na0, na1, nw0, nw1;
        if (notlast) {
            na0 = *reinterpret_cast<const float4*>(&Arow[kt + 16 + ak]);
            na1 = *reinterpret_cast<const float4*>(&Arow[kt + 16 + ak + 4]);
            nw0 = *reinterpret_cast<const float4*>(&W[(long long)(kt + 16 + wr) * Kout + nt + wc]);
            nw1 = *reinterpret_cast<const float4*>(&W[(long long)(kt + 16 + wr) * Kout + nt + wc + 4]);
        }
        const float* Ab = As[buf];
        const float* Wb = Ws[buf];
        #pragma unroll
        for (int ks = 0; ks < 16; ks += 8) {
            uint32_t af[2][4];
            #pragma unroll
            for (int mi = 0; mi < 2; mi++) {
                int r0 = m0w + mi * 16 + g;
                af[mi][0] = __float_as_uint(Ab[(r0    ) * PA + ks + t4    ]);
                af[mi][1] = __float_as_uint(Ab[(r0 + 8) * PA + ks + t4    ]);
                af[mi][2] = __float_as_uint(Ab[(r0    ) * PA + ks + t4 + 4]);
                af[mi][3] = __float_as_uint(Ab[(r0 + 8) * PA + ks + t4 + 4]);
            }
            uint32_t bf[8][2];
            #pragma unroll
            for (int ni = 0; ni < 8; ni++) {
                int c0 = n0w + ni * 8 + g;
                bf[ni][0] = __float_as_uint(Wb[(ks + t4    ) * PW + c0]);
                bf[ni][1] = __float_as_uint(Wb[(ks + t4 + 4) * PW + c0]);
            }
            #pragma unroll
            for (int mi = 0; mi < 2; mi++)
                #pragma unroll
                for (int ni = 0; ni < 8; ni++)
                    mma_tf32(acc[mi][ni], af[mi][0], af[mi][1], af[mi][2], af[mi][3],
                             bf[ni][0], bf[ni][1]);
        }
        if (notlast) {
            int nb = buf ^ 1;
            float* d = &As[nb][ar * PA + ak];
            d[0] = to_tf32(na0.x); d[1] = to_tf32(na0.y); d[2] = to_tf32(na0.z); d[3] = to_tf32(na0.w);
            d[4] = to_tf32(na1.x); d[5] = to_tf32(na1.y); d[6] = to_tf32(na1.z); d[7] = to_tf32(na1.w);
            float* e = &Ws[nb][wr * PW + wc];
            e[0] = to_tf32(nw0.x); e[1] = to_tf32(nw0.y); e[2] = to_tf32(nw0.z); e[3] = to_tf32(nw0.w);
            e[4] = to_tf32(nw1.x); e[5] = to_tf32(nw1.y); e[6] = to_tf32(nw1.z); e[7] = to_tf32(nw1.w);
            __syncthreads();
        }
        buf ^= 1;
    }

    #pragma unroll
    for (int mi = 0; mi < 2; mi++) {
        #pragma unroll
        for (int ni = 0; ni < 8; ni++) {
            int row = mt + m0w + mi * 16 + g;
            int col = nt + n0w + ni * 8 + 2 * t4;
            float4 v = acc[mi][ni];
            *reinterpret_cast<float2*>(&C[(long long)row * Kout + col]) = make_float2(v.x, v.y);
            *reinterpret_cast<float2*>(&C[(long long)(row + 8) * Kout + col]) = make_float2(v.z, v.w);
        }
    }
}

// ============================================================
// Kernel 5a: fused score + sort + scalar scans + per-i coeffs.
// ============================================================
__global__ void sortscan_kernel(const float* __restrict__ h, const float* __restrict__ att,
                                int* __restrict__ sidx_g, float* __restrict__ e1_g,
                                float* __restrict__ e2_g, int* __restrict__ t_g,
                                float* __restrict__ c1_g, float* __restrict__ c2_g,
                                float* __restrict__ ns_g) {
    int bh = blockIdx.x;
    int b = bh >> 2, hd = bh & 3;
    int i = threadIdx.x;
    __shared__ float satt[128];
    __shared__ float sv[N_];
    __shared__ int   si[N_];
    __shared__ float sP1[N_ + 1], sP2[N_ + 1];
    __shared__ float sbuf[N_];

    if (i < 128) satt[i] = att[hd * 128 + i];
    __syncthreads();

    const float4* hrow = reinterpret_cast<const float4*>(&h[((long long)(b * N_ + i)) * C_ + hd * 64]);
    float a = 0.f, bval = 0.f;
    #pragma unroll
    for (int q = 0; q < 16; q++) {
        float4 v = hrow[q];
        float4 w1 = *reinterpret_cast<const float4*>(&satt[q * 4]);
        float4 w2 = *reinterpret_cast<const float4*>(&satt[64 + q * 4]);
        a    += v.x * w1.x + v.y * w1.y + v.z * w1.z + v.w * w1.w;
        bval += v.x * w2.x + v.y * w2.y + v.z * w2.z + v.w * w2.w;
    }

    sbuf[i] = bval; __syncthreads();
    #pragma unroll
    for (int o = 256; o > 0; o >>= 1) {
        if (i < o) sbuf[i] = fmaxf(sbuf[i], sbuf[i + o]);
        __syncthreads();
    }
    float mb = sbuf[0];
    __syncthreads();

    sv[i] = bval - mb; si[i] = i;
    __syncthreads();
    for (int k = 2; k <= N_; k <<= 1) {
        for (int j = k >> 1; j > 0; j >>= 1) {
            int l = i ^ j;
            if (l > i) {
                bool up = ((i & k) == 0);
                float v0 = sv[i], v1 = sv[l];
                if ((v0 > v1) == up) {
                    sv[i] = v1; sv[l] = v0;
                    int t0 = si[i]; si[i] = si[l]; si[l] = t0;
                }
            }
            __syncthreads();
        }
    }

    float e1 = __expf(sv[i]);
    float e2 = __expf(0.2f * sv[i]);

    sbuf[i] = e2; __syncthreads();
    for (int o = 1; o < N_; o <<= 1) {
        float v = sbuf[i];
        if (i >= o) v += sbuf[i - o];
        __syncthreads();
        sbuf[i] = v;
        __syncthreads();
    }
    sP2[i + 1] = sbuf[i];
    if (i == 0) sP2[0] = 0.f;
    __syncthreads();
    sbuf[i] = e1; __syncthreads();
    for (int o = 1; o < N_; o <<= 1) {
        float v = sbuf[i];
        if (i + o < N_) v += sbuf[i + o];
        __syncthreads();
        sbuf[i] = v;
        __syncthreads();
    }
    sP1[i] = sbuf[i];
    if (i == 0) sP1[N_] = 0.f;
    __syncthreads();

    sidx_g[bh * N_ + i] = si[i];
    e1_g[bh * N_ + i] = e1;
    e2_g[bh * N_ + i] = e2;

    float thr = -a - mb;
    int lo = 0, hi = N_;
    while (lo < hi) {
        int mid = (lo + hi) >> 1;
        if (sv[mid] > thr) hi = mid; else lo = mid + 1;
    }
    int t = lo;
    float s = a + mb;
    float m = s > 0.f ? s : 0.2f * s;
    float c1v = __expf(s - m);
    float c2v = __expf(0.2f * s - m);
    float sci = a + bval;
    float lsci = sci > 0.f ? sci : 0.2f * sci;
    float ns = __expf(lsci - m);
    float Z = c1v * sP1[t] + c2v * sP2[t] - ns;
    float rz = 1.f / fmaxf(Z, 1e-35f);
    t_g [bh * N_ + i] = t;
    c1_g[bh * N_ + i] = c1v * rz;
    c2_g[bh * N_ + i] = c2v * rz;
    ns_g[bh * N_ + i] = ns * rz;
}

// ============================================================
// Kernel 5b: FUSED vector scans + emit. One block (512 thr) per (b,h).
// Two-level scan: warp w owns sorted chunk w (32 k's); chunk-local
// inclusive scans via shfl; 16-chunk bases added lazily at emit lookup.
// V1h/V2h/tile live entirely in smem; f processed in two 32-wide halves.
// ============================================================
__global__ void __launch_bounds__(512, 1)
fusedscan_kernel(const float* __restrict__ h,
                 const int* __restrict__ sidx_g,
                 const float* __restrict__ e1_g, const float* __restrict__ e2_g,
                 const int* __restrict__ t_g, const float* __restrict__ c1_g,
                 const float* __restrict__ c2_g, const float* __restrict__ ns_g,
                 float* __restrict__ out, int dorelu) {
    __shared__ float tile[N_][33];          // sorted h, current f-half
    __shared__ float V1h[N_ + 1][33];       // chunk-local inclusive suffix (e1*h)
    __shared__ float V2h[N_ + 1][33];       // chunk-local exclusive prefix (e2*h)
    __shared__ float tot1[16][32], tot2[16][32];
    __shared__ float suf1[17][32], pre2[17][32];
    __shared__ int   sIdx[N_];
    __shared__ int   sT[N_];
    __shared__ float sC1[N_], sC2[N_], sNS[N_];

    int bh = blockIdx.x;
    int b = bh >> 2, hd = bh & 3;
    int tid = threadIdx.x;
    int w = tid >> 5, l = tid & 31;

    sIdx[tid] = sidx_g[bh * N_ + tid];
    sT[tid]   = t_g [bh * N_ + tid];
    sC1[tid]  = c1_g[bh * N_ + tid];
    sC2[tid]  = c2_g[bh * N_ + tid];
    sNS[tid]  = ns_g[bh * N_ + tid];
    float ev1 = e1_g[bh * N_ + tid];   // k == tid (sorted position)
    float ev2 = e2_g[bh * N_ + tid];
    if (tid < 32) { V1h[N_][tid] = 0.f; V2h[N_][tid] = 0.f; }

    const float* hb = h + (long long)b * N_ * C_ + hd * 64;

    #pragma unroll
    for (int half = 0; half < 2; half++) {
        int fo = half * 32;
        __syncthreads();   // protect tile/V reuse (and initial smem loads)

        // gather sorted h rows (32 floats each) into tile
        #pragma unroll
        for (int it = 0; it < 8; it++) {
            int idx = it * 512 + tid;
            int k = idx >> 3, q = idx & 7;
            float4 v = *reinterpret_cast<const float4*>(
                &hb[(long long)sIdx[k] * C_ + fo + q * 4]);
            tile[k][q * 4 + 0] = v.x; tile[k][q * 4 + 1] = v.y;
            tile[k][q * 4 + 2] = v.z; tile[k][q * 4 + 3] = v.w;
        }
        __syncthreads();

        // pass 1: chunk-local scans (warp w = chunk w, all 8 f-quads)
        #pragma unroll
        for (int j = 0; j < 8; j++) {
            int f0 = j * 4;
            float x1[4], x2[4], p1[4], p2[4];
            #pragma unroll
            for (int ff = 0; ff < 4; ff++) {
                float hv = tile[tid][f0 + ff];
                x1[ff] = ev1 * hv; x2[ff] = ev2 * hv;
                p1[ff] = x1[ff];  p2[ff] = x2[ff];
            }
            #pragma unroll
            for (int off = 1; off < 32; off <<= 1) {
                #pragma unroll
                for (int ff = 0; ff < 4; ff++) {
                    float nu = __shfl_up_sync(0xffffffffu, p2[ff], off);
                    float nd = __shfl_down_sync(0xffffffffu, p1[ff], off);
                    if (l >= off)     p2[ff] += nu;
                    if (l + off < 32) p1[ff] += nd;
                }
            }
            #pragma unroll
            for (int ff = 0; ff < 4; ff++) {
                V2h[tid][f0 + ff] = p2[ff] - x2[ff];   // exclusive prefix
                V1h[tid][f0 + ff] = p1[ff];            // inclusive suffix
            }
            if (l == 31) {
                #pragma unroll
                for (int ff = 0; ff < 4; ff++) tot2[w][f0 + ff] = p2[ff];
            }
            if (l == 0) {
                #pragma unroll
                for (int ff = 0; ff < 4; ff++) tot1[w][f0 + ff] = p1[ff];
            }
        }
        __syncthreads();

        // pass 2: chunk bases (serial over 16 chunks, per f)
        if (tid < 32) {
            int f = tid;
            float pre = 0.f;
            #pragma unroll
            for (int c = 0; c < 16; c++) { pre2[c][f] = pre; pre += tot2[c][f]; }
            pre2[16][f] = pre;
        } else if (tid < 64) {
            int f = tid - 32;
            float s = 0.f;
            suf1[16][f] = 0.f;
            #pragma unroll
            for (int c = 15; c >= 0; c--) { suf1[c][f] = s; s += tot1[c][f]; }
        }
        __syncthreads();

        // pass 3: emit. thread = sorted position k; i = sIdx[k].
        {
            int i = sIdx[tid];
            int t = sT[i];
            float c1 = sC1[i], c2 = sC2[i], ns = sNS[i];
            int tc = t >> 5;
            float* outp = out + ((long long)(b * N_ + i)) * C_ + hd * 64 + fo;
            #pragma unroll
            for (int q = 0; q < 8; q++) {
                float4 o;
                float* po = &o.x;
                #pragma unroll
                for (int ff = 0; ff < 4; ff++) {
                    int f = q * 4 + ff;
                    float v1 = V1h[t][f] + suf1[tc][f];
                    float v2 = V2h[t][f] + pre2[tc][f];
                    float val = c1 * v1 + c2 * v2 - ns * tile[tid][f];
                    po[ff] = dorelu ? fmaxf(val, 0.f) : val;
                }
                *reinterpret_cast<float4*>(outp + q * 4) = o;
            }
        }
    }
}

// ============================================================
// launch
// ============================================================
extern "C" void kernel_launch(void* const* d_in, const int* in_sizes, int n_in,
                              void* d_out, int out_size) {
    int off = (n_in >= 16) ? 1 : 0;
    const int*   player = (const int*)  d_in[0];
    const int*   shot   = (const int*)  d_in[1];
    const float* Ax     = (const float*)d_in[2];
    const float* Ay     = (const float*)d_in[3];
    const float* Bx     = (const float*)d_in[4];
    const float* By     = (const float*)d_in[5];
    const float* emb    = (const float*)d_in[6 + off];
    const float* Wc     = (const float*)d_in[7 + off];
    const float* bc     = (const float*)d_in[8 + off];
    const float* Wm     = (const float*)d_in[9 + off];
    const float* bm     = (const float*)d_in[10 + off];
    const float* lin1   = (const float*)d_in[11 + off];
    const float* att1   = (const float*)d_in[12 + off];
    const float* lin2   = (const float*)d_in[13 + off];
    const float* att2   = (const float*)d_in[14 + off];

    float* out_ne  = (float*)d_out;
    float* out_adj = out_ne + NE_ELEMS;

    float *px, *ph, *po1;
    float *pe1, *pe2, *pc1, *pc2, *pns;
    int *psidx, *pt;
    cudaGetSymbolAddress((void**)&px,  g_x);
    cudaGetSymbolAddress((void**)&ph,  g_h);
    cudaGetSymbolAddress((void**)&po1, g_o1);
    cudaGetSymbolAddress((void**)&psidx, g_sidx);
    cudaGetSymbolAddress((void**)&pe1, g_e1);
    cudaGetSymbolAddress((void**)&pe2, g_e2);
    cudaGetSymbolAddress((void**)&pt,  g_t);
    cudaGetSymbolAddress((void**)&pc1, g_c1);
    cudaGetSymbolAddress((void**)&pc2, g_c2);
    cudaGetSymbolAddress((void**)&pns, g_ns);

    int need_adj = (out_size >= NE_ELEMS + ADJ_ELEMS) ? 1 : 0;

    feat_kernel<<<B_ * 16, 256>>>(player, Ax, Ay, Bx, By, emb, Wc, bc, Wm, bm, px);

    dim3 ggrid1(2, MROWS + (need_adj ? FILL_A / 2 : 0));
    dim3 ggrid2(2, MROWS + (need_adj ? FILL_B / 2 : 0));

    // ---- layer 1 ----
    gemm_fill_kernel<HID><<<ggrid1, 256>>>(px, lin1, ph, out_adj, 0);
    sortscan_kernel<<<BH_, N_>>>(ph, att1, psidx, pe1, pe2, pt, pc1, pc2, pns);
    fusedscan_kernel<<<BH_, 512>>>(ph, psidx, pe1, pe2, pt, pc1, pc2, pns, po1, 1);

    // ---- layer 2 ----
    gemm_fill_kernel<C_><<<ggrid2, 256>>>(po1, lin2, ph, out_adj, FILL_A);
    sortscan_kernel<<<BH_, N_>>>(ph, att2, psidx, pe1, pe2, pt, pc1, pc2, pns);
    fusedscan_kernel<<<BH_, 512>>>(ph, psidx, pe1, pe2, pt, pc1, pc2, pns, out_ne, 0);

    if (need_adj) scatter_kernel<<<(B_ * S_ + 255) / 256, 256>>>(shot, out_adj);
}

// round 8
// speedup vs baseline: 2.5081x; 1.0344x over previous
#include <cuda_runtime.h>
#include <cstdint>

// ---------------- problem constants ----------------
#define B_    32
#define E_    256
#define N_    512
#define HID   64
#define H_    4
#define F_    64
#define C_    256
#define S_    255
#define BH_   (B_*H_)
#define NE_ELEMS (B_*N_*C_)
#define ADJ_ELEMS (B_*14*N_*N_)
#define MROWS ((B_*N_)/128)
#define FILL_TOTAL (32*14*32)
#define FILL_A (FILL_TOTAL/2)
#define FILL_B (FILL_TOTAL - FILL_A)

#define PA 20
#define PW 136
#define FQ 8          // channels per fusedscan block
#define PV 9          // V pitch (odd => conflict-free)

// ---------------- scratch ----------------
__device__ float g_x  [B_*N_*HID];
__device__ float g_h  [B_*N_*C_];
__device__ float g_o1 [B_*N_*C_];
__device__ int   g_sidx[BH_*N_];
__device__ float g_e1 [BH_*N_];
__device__ float g_e2 [BH_*N_];
__device__ int   g_t  [BH_*N_];
__device__ float g_c1 [BH_*N_];
__device__ float g_c2 [BH_*N_];
__device__ float g_ns [BH_*N_];

__device__ __forceinline__ float to_tf32(float x) {
    float r; asm("cvt.rna.tf32.f32 %0, %1;" : "=f"(r) : "f"(x)); return r;
}

__device__ __forceinline__ void mma_tf32(float4& d,
                                         uint32_t a0, uint32_t a1, uint32_t a2, uint32_t a3,
                                         uint32_t b0, uint32_t b1) {
    asm("mma.sync.aligned.m16n8k8.row.col.f32.tf32.tf32.f32 "
        "{%0,%1,%2,%3},{%4,%5,%6,%7},{%8,%9},{%0,%1,%2,%3};"
        : "+f"(d.x), "+f"(d.y), "+f"(d.z), "+f"(d.w)
        : "r"(a0), "r"(a1), "r"(a2), "r"(a3), "r"(b0), "r"(b1));
}

// ============================================================
// Adjacency fill (one 256-thread block's share).
// ============================================================
__device__ __forceinline__ void fill_block(int fid, int t, float* __restrict__ out) {
    int x = fid & 31;
    int rest = fid >> 5;
    int r = rest % 14;
    int b = rest / 14;
    int n  = x * 16 + (t >> 4);
    int m0 = (t & 15) * 32;
    float* p = out + ((((long long)b * 14 + r) * N_ + n) << 9) + m0;
    float4* p4 = reinterpret_cast<float4*>(p);

    if (r < 13) {
        float4 z = make_float4(0.f, 0.f, 0.f, 0.f);
        #pragma unroll
        for (int q = 0; q < 8; q++) __stcs(p4 + q, z);
        if (r >= 11) {
            int cu = n + 2;
            if (cu < N_ && cu >= m0 && cu < m0 + 32) {
                int rel = ((n & 3) == 0 || (n & 3) == 3) ? 11 : 12;
                if (rel == r) p[cu - m0] = 1.f;
            }
            int cd = n - 2;
            if (cd >= 0 && cd >= m0 && cd < m0 + 32) {
                int pp = n - 2;
                int rel = ((pp & 3) == 0 || (pp & 3) == 3) ? 11 : 12;
                if (rel == r) p[cd - m0] = 1.f;
            }
        }
        return;
    }
    if (n + 3 < m0 || n - 3 >= m0 + 32) {
        float4 o1 = make_float4(1.f, 1.f, 1.f, 1.f);
        #pragma unroll
        for (int q = 0; q < 8; q++) __stcs(p4 + q, o1);
        return;
    }
    int sp1 = -1, sp2 = -1;
    int nm = n & 3;
    if (nm == 0) {
        if (n <= 508) sp1 = n + 3;
        if (n >= 4)   sp2 = n - 1;
    } else if (nm == 3) {
        if (n <= 507) sp1 = n + 1;
        sp2 = n - 3;
    }
    float vals[32];
    #pragma unroll
    for (int q = 0; q < 32; q++) {
        int m = m0 + q;
        bool zero = (m == n) | (m == n - 2) | (m == n + 2) | (m == sp1) | (m == sp2);
        vals[q] = zero ? 0.f : 1.f;
    }
    #pragma unroll
    for (int q = 0; q < 8; q++)
        __stcs(p4 + q, make_float4(vals[4*q], vals[4*q+1], vals[4*q+2], vals[4*q+3]));
}

__global__ void scatter_kernel(const int* __restrict__ shot, float* __restrict__ out) {
    int idx = blockIdx.x * 256 + threadIdx.x;
    if (idx >= B_ * S_) return;
    int b = idx / S_, s = idx % S_;
    int r = shot[idx];
    int i, j;
    if ((s & 1) == 0) { i = 2 * s;     j = 2 * s + 3; }
    else              { i = 2 * s + 1; j = 2 * s + 2; }
    long long base = ((long long)b * 14 + r) * (N_ * N_);
    out[base + (long long)i * N_ + j] = 1.f;
    out[base + (long long)j * N_ + i] = 1.f;
}

// ============================================================
// Kernel 2: node features.
// ============================================================
__global__ void feat_kernel(const int* __restrict__ player,
                            const float* __restrict__ Ax, const float* __restrict__ Ay,
                            const float* __restrict__ Bx, const float* __restrict__ By,
                            const float* __restrict__ emb,
                            const float* __restrict__ Wc, const float* __restrict__ bc,
                            const float* __restrict__ Wm, const float* __restrict__ bm,
                            float* __restrict__ x) {
    __shared__ float feat[32][64];
    __shared__ float wms[64 * 64];
    int blk = blockIdx.x;
    int b = blk >> 4;
    int n0 = (blk & 15) * 32;
    int tid = threadIdx.x;

    #pragma unroll
    for (int it = 0; it < 16; it++) wms[it * 256 + tid] = Wm[it * 256 + tid];

    #pragma unroll
    for (int it = 0; it < 8; it++) {
        int o = it * 256 + tid;
        int nl = o >> 6, c = o & 63;
        int n = n0 + nl;
        int e = n >> 1;
        float val;
        if (c < 32) {
            float cx, cy;
            if ((n & 1) == 0) { cx = Ax[b * E_ + e]; cy = Ay[b * E_ + e]; }
            else              { cx = Bx[b * E_ + e]; cy = By[b * E_ + e]; }
            val = fmaxf(cx * Wc[c] + cy * Wc[32 + c] + bc[c], 0.f);
        } else {
            int pid = player[b * 2 + (n & 1)];
            val = emb[pid * 32 + (c - 32)];
        }
        feat[nl][c] = val;
    }
    __syncthreads();

    #pragma unroll
    for (int it = 0; it < 8; it++) {
        int o = it * 256 + tid;
        int nl = o >> 6, k = o & 63;
        float acc = bm[k];
        #pragma unroll
        for (int c = 0; c < 64; c++) acc += feat[nl][c] * wms[c * 64 + k];
        x[(b * N_ + n0 + nl) * HID + k] = acc;
    }
}

// ============================================================
// Kernel 3: hybrid tf32-MMA SGEMM + adjacency fill.
// ============================================================
template<int KIN>
__global__ void __launch_bounds__(256, 2)
gemm_fill_kernel(const float* __restrict__ A, const float* __restrict__ W,
                 float* __restrict__ C, float* __restrict__ adj, int fill_base) {
    if (blockIdx.y >= MROWS) {
        int fid = fill_base + (blockIdx.y - MROWS) * 2 + blockIdx.x;
        fill_block(fid, threadIdx.x, adj);
        return;
    }
    __shared__ float As[2][128 * PA];
    __shared__ float Ws[2][16 * PW];
    const int Kout = C_;
    int tid = threadIdx.x;
    int mt = blockIdx.y * 128, nt = blockIdx.x * 128;
    int wid = tid >> 5, lane = tid & 31;
    int g = lane >> 2, t4 = lane & 3;
    int m0w = (wid >> 1) * 32;
    int n0w = (wid & 1) * 64;

    int ar = tid >> 1;
    int ak = (tid & 1) * 8;
    int wr = tid >> 4;
    int wc = (tid & 15) * 8;

    float4 acc[2][8];
    #pragma unroll
    for (int mi = 0; mi < 2; mi++)
        #pragma unroll
        for (int ni = 0; ni < 8; ni++) acc[mi][ni] = make_float4(0.f, 0.f, 0.f, 0.f);

    const float* Arow = &A[(long long)(mt + ar) * KIN];

    {
        float4 a0 = *reinterpret_cast<const float4*>(&Arow[ak]);
        float4 a1 = *reinterpret_cast<const float4*>(&Arow[ak + 4]);
        float* d = &As[0][ar * PA + ak];
        d[0] = to_tf32(a0.x); d[1] = to_tf32(a0.y); d[2] = to_tf32(a0.z); d[3] = to_tf32(a0.w);
        d[4] = to_tf32(a1.x); d[5] = to_tf32(a1.y); d[6] = to_tf32(a1.z); d[7] = to_tf32(a1.w);
        float4 w0 = *reinterpret_cast<const float4*>(&W[(long long)wr * Kout + nt + wc]);
        float4 w1 = *reinterpret_cast<const float4*>(&W[(long long)wr * Kout + nt + wc + 4]);
        float* e = &Ws[0][wr * PW + wc];
        e[0] = to_tf32(w0.x); e[1] = to_tf32(w0.y); e[2] = to_tf32(w0.z); e[3] = to_tf32(w0.w);
        e[4] = to_tf32(w1.x); e[5] = to_tf32(w1.y); e[6] = to_tf32(w1.z); e[7] = to_tf32(w1.w);
    }
    __syncthreads();

    int buf = 0;
    for (int kt = 0; kt < KIN; kt += 16) {
        bool notlast = (kt + 16 < KIN);
        float4 na0, na1, nw0, nw1;
        if (notlast) {
            na0 = *reinterpret_cast<const float4*>(&Arow[kt + 16 + ak]);
            na1 = *reinterpret_cast<const float4*>(&Arow[kt + 16 + ak + 4]);
            nw0 = *reinterpret_cast<const float4*>(&W[(long long)(kt + 16 + wr) * Kout + nt + wc]);
            nw1 = *reinterpret_cast<const float4*>(&W[(long long)(kt + 16 + wr) * Kout + nt + wc + 4]);
        }
        const float* Ab = As[buf];
        const float* Wb = Ws[buf];
        #pragma unroll
        for (int ks = 0; ks < 16; ks += 8) {
            uint32_t af[2][4];
            #pragma unroll
            for (int mi = 0; mi < 2; mi++) {
                int r0 = m0w + mi * 16 + g;
                af[mi][0] = __float_as_uint(Ab[(r0    ) * PA + ks + t4    ]);
                af[mi][1] = __float_as_uint(Ab[(r0 + 8) * PA + ks + t4    ]);
                af[mi][2] = __float_as_uint(Ab[(r0    ) * PA + ks + t4 + 4]);
                af[mi][3] = __float_as_uint(Ab[(r0 + 8) * PA + ks + t4 + 4]);
            }
            uint32_t bf[8][2];
            #pragma unroll
            for (int ni = 0; ni < 8; ni++) {
                int c0 = n0w + ni * 8 + g;
                bf[ni][0] = __float_as_uint(Wb[(ks + t4    ) * PW + c0]);
                bf[ni][1] = __float_as_uint(Wb[(ks + t4 + 4) * PW + c0]);
            }
            #pragma unroll
            for (int mi = 0; mi < 2; mi++)
                #pragma unroll
                for (int ni = 0; ni < 8; ni++)
                    mma_tf32(acc[mi][ni], af[mi][0], af[mi][1], af[mi][2], af[mi][3],
                             bf[ni][0], bf[ni][1]);
        }
        if (notlast) {
            int nb = buf ^ 1;
            float* d = &As[nb][ar * PA + ak];
            d[0] = to_tf32(na0.x); d[1] = to_tf32(na0.y); d[2] = to_tf32(na0.z); d[3] = to_tf32(na0.w);
            d[4] = to_tf32(na1.x); d[5] = to_tf32(na1.y); d[6] = to_tf32(na1.z); d[7] = to_tf32(na1.w);
            float* e = &Ws[nb][wr * PW + wc];
            e[0] = to_tf32(nw0.x); e[1] = to_tf32(nw0.y); e[2] = to_tf32(nw0.z); e[3] = to_tf32(nw0.w);
            e[4] = to_tf32(nw1.x); e[5] = to_tf32(nw1.y); e[6] = to_tf32(nw1.z); e[7] = to_tf32(nw1.w);
            __syncthreads();
        }
        buf ^= 1;
    }

    #pragma unroll
    for (int mi = 0; mi < 2; mi++) {
        #pragma unroll
        for (int ni = 0; ni < 8; ni++) {
            int row = mt + m0w + mi * 16 + g;
            int col = nt + n0w + ni * 8 + 2 * t4;
            float4 v = acc[mi][ni];
            *reinterpret_cast<float2*>(&C[(long long)row * Kout + col]) = make_float2(v.x, v.y);
            *reinterpret_cast<float2*>(&C[(long long)(row + 8) * Kout + col]) = make_float2(v.z, v.w);
        }
    }
}

// ============================================================
// Kernel 5a: fused score + sort + scalar scans + per-i coeffs.
// ============================================================
__global__ void sortscan_kernel(const float* __restrict__ h, const float* __restrict__ att,
                                int* __restrict__ sidx_g, float* __restrict__ e1_g,
                                float* __restrict__ e2_g, int* __restrict__ t_g,
                                float* __restrict__ c1_g, float* __restrict__ c2_g,
                                float* __restrict__ ns_g) {
    int bh = blockIdx.x;
    int b = bh >> 2, hd = bh & 3;
    int i = threadIdx.x;
    __shared__ float satt[128];
    __shared__ float sv[N_];
    __shared__ int   si[N_];
    __shared__ float sP1[N_ + 1], sP2[N_ + 1];
    __shared__ float sbuf[N_];

    if (i < 128) satt[i] = att[hd * 128 + i];
    __syncthreads();

    const float4* hrow = reinterpret_cast<const float4*>(&h[((long long)(b * N_ + i)) * C_ + hd * 64]);
    float a = 0.f, bval = 0.f;
    #pragma unroll
    for (int q = 0; q < 16; q++) {
        float4 v = hrow[q];
        float4 w1 = *reinterpret_cast<const float4*>(&satt[q * 4]);
        float4 w2 = *reinterpret_cast<const float4*>(&satt[64 + q * 4]);
        a    += v.x * w1.x + v.y * w1.y + v.z * w1.z + v.w * w1.w;
        bval += v.x * w2.x + v.y * w2.y + v.z * w2.z + v.w * w2.w;
    }

    sbuf[i] = bval; __syncthreads();
    #pragma unroll
    for (int o = 256; o > 0; o >>= 1) {
        if (i < o) sbuf[i] = fmaxf(sbuf[i], sbuf[i + o]);
        __syncthreads();
    }
    float mb = sbuf[0];
    __syncthreads();

    sv[i] = bval - mb; si[i] = i;
    __syncthreads();
    for (int k = 2; k <= N_; k <<= 1) {
        for (int j = k >> 1; j > 0; j >>= 1) {
            int l = i ^ j;
            if (l > i) {
                bool up = ((i & k) == 0);
                float v0 = sv[i], v1 = sv[l];
                if ((v0 > v1) == up) {
                    sv[i] = v1; sv[l] = v0;
                    int t0 = si[i]; si[i] = si[l]; si[l] = t0;
                }
            }
            __syncthreads();
        }
    }

    float e1 = __expf(sv[i]);
    float e2 = __expf(0.2f * sv[i]);

    sbuf[i] = e2; __syncthreads();
    for (int o = 1; o < N_; o <<= 1) {
        float v = sbuf[i];
        if (i >= o) v += sbuf[i - o];
        __syncthreads();
        sbuf[i] = v;
        __syncthreads();
    }
    sP2[i + 1] = sbuf[i];
    if (i == 0) sP2[0] = 0.f;
    __syncthreads();
    sbuf[i] = e1; __syncthreads();
    for (int o = 1; o < N_; o <<= 1) {
        float v = sbuf[i];
        if (i + o < N_) v += sbuf[i + o];
        __syncthreads();
        sbuf[i] = v;
        __syncthreads();
    }
    sP1[i] = sbuf[i];
    if (i == 0) sP1[N_] = 0.f;
    __syncthreads();

    sidx_g[bh * N_ + i] = si[i];
    e1_g[bh * N_ + i] = e1;
    e2_g[bh * N_ + i] = e2;

    float thr = -a - mb;
    int lo = 0, hi = N_;
    while (lo < hi) {
        int mid = (lo + hi) >> 1;
        if (sv[mid] > thr) hi = mid; else lo = mid + 1;
    }
    int t = lo;
    float s = a + mb;
    float m = s > 0.f ? s : 0.2f * s;
    float c1v = __expf(s - m);
    float c2v = __expf(0.2f * s - m);
    float sci = a + bval;
    float lsci = sci > 0.f ? sci : 0.2f * sci;
    float ns = __expf(lsci - m);
    float Z = c1v * sP1[t] + c2v * sP2[t] - ns;
    float rz = 1.f / fmaxf(Z, 1e-35f);
    t_g [bh * N_ + i] = t;
    c1_g[bh * N_ + i] = c1v * rz;
    c2_g[bh * N_ + i] = c2v * rz;
    ns_g[bh * N_ + i] = ns * rz;
}

// ============================================================
// Kernel 5b: FUSED vector scans + emit, f-sliced.
// Block = (bh, f-slice of 8 channels); 512 threads; thread k owns sorted
// position k with its 8-channel h-row slice in registers. Two-level scan:
// chunk-local shfl scans + lazy chunk bases at emit lookup.
// ============================================================
__global__ void __launch_bounds__(512, 2)
fusedscan_kernel(const float* __restrict__ h,
                 const int* __restrict__ sidx_g,
                 const float* __restrict__ e1_g, const float* __restrict__ e2_g,
                 const int* __restrict__ t_g, const float* __restrict__ c1_g,
                 const float* __restrict__ c2_g, const float* __restrict__ ns_g,
                 float* __restrict__ out, int dorelu) {
    __shared__ float V1h[N_ + 1][PV];
    __shared__ float V2h[N_ + 1][PV];
    __shared__ float tot1[16][FQ], tot2[16][FQ];
    __shared__ float suf1[17][FQ], pre2[17][FQ];
    __shared__ int   sIdx[N_];
    __shared__ int   sT[N_];
    __shared__ float sC1[N_], sC2[N_], sNS[N_];

    int bh = blockIdx.x;
    int fo = blockIdx.y * FQ;
    int b = bh >> 2, hd = bh & 3;
    int tid = threadIdx.x;
    int w = tid >> 5, l = tid & 31;

    int myIdx = sidx_g[bh * N_ + tid];
    sIdx[tid] = myIdx;
    sT[tid]   = t_g [bh * N_ + tid];
    sC1[tid]  = c1_g[bh * N_ + tid];
    sC2[tid]  = c2_g[bh * N_ + tid];
    sNS[tid]  = ns_g[bh * N_ + tid];
    float ev1 = e1_g[bh * N_ + tid];
    float ev2 = e2_g[bh * N_ + tid];
    if (tid < FQ) { V1h[N_][tid] = 0.f; V2h[N_][tid] = 0.f; }

    // gather my sorted row slice into registers
    const float* hb = h + (long long)b * N_ * C_ + hd * 64 + fo;
    float hv[FQ];
    {
        float4 v0 = *reinterpret_cast<const float4*>(&hb[(long long)myIdx * C_]);
        float4 v1 = *reinterpret_cast<const float4*>(&hb[(long long)myIdx * C_ + 4]);
        hv[0] = v0.x; hv[1] = v0.y; hv[2] = v0.z; hv[3] = v0.w;
        hv[4] = v1.x; hv[5] = v1.y; hv[6] = v1.z; hv[7] = v1.w;
    }

    // pass 1: chunk-local scans (warp w = sorted chunk w)
    float p1[FQ], p2[FQ];
    #pragma unroll
    for (int f = 0; f < FQ; f++) { p1[f] = ev1 * hv[f]; p2[f] = ev2 * hv[f]; }
    #pragma unroll
    for (int off = 1; off < 32; off <<= 1) {
        #pragma unroll
        for (int f = 0; f < FQ; f++) {
            float nu = __shfl_up_sync(0xffffffffu, p2[f], off);
            float nd = __shfl_down_sync(0xffffffffu, p1[f], off);
            if (l >= off)     p2[f] += nu;
            if (l + off < 32) p1[f] += nd;
        }
    }
    #pragma unroll
    for (int f = 0; f < FQ; f++) {
        V2h[tid][f] = p2[f] - ev2 * hv[f];   // exclusive prefix (chunk-local)
        V1h[tid][f] = p1[f];                 // inclusive suffix (chunk-local)
    }
    if (l == 31) {
        #pragma unroll
        for (int f = 0; f < FQ; f++) tot2[w][f] = p2[f];
    }
    if (l == 0) {
        #pragma unroll
        for (int f = 0; f < FQ; f++) tot1[w][f] = p1[f];
    }
    __syncthreads();

    // pass 2: chunk bases
    if (tid < FQ) {
        int f = tid;
        float pre = 0.f;
        #pragma unroll
        for (int c = 0; c < 16; c++) { pre2[c][f] = pre; pre += tot2[c][f]; }
        pre2[16][f] = pre;
    } else if (tid < 2 * FQ) {
        int f = tid - FQ;
        float s = 0.f;
        suf1[16][f] = 0.f;
        #pragma unroll
        for (int c = 15; c >= 0; c--) { suf1[c][f] = s; s += tot1[c][f]; }
    }
    __syncthreads();

    // pass 3: emit row i = myIdx
    {
        int i = myIdx;
        int t = sT[i];
        float c1 = sC1[i], c2 = sC2[i], ns = sNS[i];
        int tc = t >> 5;
        float o[FQ];
        #pragma unroll
        for (int f = 0; f < FQ; f++) {
            float v1 = V1h[t][f] + suf1[tc][f];
            float v2 = V2h[t][f] + pre2[tc][f];
            float val = c1 * v1 + c2 * v2 - ns * hv[f];
            o[f] = dorelu ? fmaxf(val, 0.f) : val;
        }
        float* outp = out + ((long long)(b * N_ + i)) * C_ + hd * 64 + fo;
        *reinterpret_cast<float4*>(outp)     = make_float4(o[0], o[1], o[2], o[3]);
        *reinterpret_cast<float4*>(outp + 4) = make_float4(o[4], o[5], o[6], o[7]);
    }
}

// ============================================================
// launch
// ============================================================
extern "C" void kernel_launch(void* const* d_in, const int* in_sizes, int n_in,
                              void* d_out, int out_size) {
    int off = (n_in >= 16) ? 1 : 0;
    const int*   player = (const int*)  d_in[0];
    const int*   shot   = (const int*)  d_in[1];
    const float* Ax     = (const float*)d_in[2];
    const float* Ay     = (const float*)d_in[3];
    const float* Bx     = (const float*)d_in[4];
    const float* By     = (const float*)d_in[5];
    const float* emb    = (const float*)d_in[6 + off];
    const float* Wc     = (const float*)d_in[7 + off];
    const float* bc     = (const float*)d_in[8 + off];
    const float* Wm     = (const float*)d_in[9 + off];
    const float* bm     = (const float*)d_in[10 + off];
    const float* lin1   = (const float*)d_in[11 + off];
    const float* att1   = (const float*)d_in[12 + off];
    const float* lin2   = (const float*)d_in[13 + off];
    const float* att2   = (const float*)d_in[14 + off];

    float* out_ne  = (float*)d_out;
    float* out_adj = out_ne + NE_ELEMS;

    float *px, *ph, *po1;
    float *pe1, *pe2, *pc1, *pc2, *pns;
    int *psidx, *pt;
    cudaGetSymbolAddress((void**)&px,  g_x);
    cudaGetSymbolAddress((void**)&ph,  g_h);
    cudaGetSymbolAddress((void**)&po1, g_o1);
    cudaGetSymbolAddress((void**)&psidx, g_sidx);
    cudaGetSymbolAddress((void**)&pe1, g_e1);
    cudaGetSymbolAddress((void**)&pe2, g_e2);
    cudaGetSymbolAddress((void**)&pt,  g_t);
    cudaGetSymbolAddress((void**)&pc1, g_c1);
    cudaGetSymbolAddress((void**)&pc2, g_c2);
    cudaGetSymbolAddress((void**)&pns, g_ns);

    int need_adj = (out_size >= NE_ELEMS + ADJ_ELEMS) ? 1 : 0;

    feat_kernel<<<B_ * 16, 256>>>(player, Ax, Ay, Bx, By, emb, Wc, bc, Wm, bm, px);

    dim3 ggrid1(2, MROWS + (need_adj ? FILL_A / 2 : 0));
    dim3 ggrid2(2, MROWS + (need_adj ? FILL_B / 2 : 0));
    dim3 fgrid(BH_, F_ / FQ);

    // ---- layer 1 ----
    gemm_fill_kernel<HID><<<ggrid1, 256>>>(px, lin1, ph, out_adj, 0);
    sortscan_kernel<<<BH_, N_>>>(ph, att1, psidx, pe1, pe2, pt, pc1, pc2, pns);
    fusedscan_kernel<<<fgrid, 512>>>(ph, psidx, pe1, pe2, pt, pc1, pc2, pns, po1, 1);

    // ---- layer 2 ----
    gemm_fill_kernel<C_><<<ggrid2, 256>>>(po1, lin2, ph, out_adj, FILL_A);
    sortscan_kernel<<<BH_, N_>>>(ph, att2, psidx, pe1, pe2, pt, pc1, pc2, pns);
    fusedscan_kernel<<<fgrid, 512>>>(ph, psidx, pe1, pe2, pt, pc1, pc2, pns, out_ne, 0);

    if (need_adj) scatter_kernel<<<(B_ * S_ + 255) / 256, 256>>>(shot, out_adj);
}